// round 1
// baseline (speedup 1.0000x reference)
#include <cuda_runtime.h>
#include <cstdint>

#define BB 8
#define NN 4096
#define CC 64
#define OUTC 64
#define NS 32
#define R2C 0.04f
#define ALPHA 0.2f

#define CAP 320
#define NWARP 8
#define CPB 128

// Scratch (device globals: allocation-free rule)
__device__ float g_featT[(size_t)BB * NN * CC];          // 8 MB, (B,N,C)
__device__ float g_projL[(size_t)BB * NN * 16 * CC];     // 134 MB, rows of 1024 = c*16+k

__device__ __forceinline__ float leaky(float x) { return fmaxf(x, ALPHA * x); }

// ---------------- Kernel 0: transpose features (B,C,N) -> (B,N,C) ----------------
__global__ void transpose_kernel(const float* __restrict__ feat) {
    __shared__ float tile[32][33];
    int b  = blockIdx.z;
    int n0 = blockIdx.x * 32;
    int c0 = blockIdx.y * 32;
    int tx = threadIdx.x, ty = threadIdx.y;  // (32,8)
    const float* fb = feat + (size_t)b * CC * NN;
    float* ob = g_featT + (size_t)b * NN * CC;
#pragma unroll
    for (int i = 0; i < 4; i++) {
        int c = c0 + ty + i * 8;
        tile[ty + i * 8][tx] = fb[(size_t)c * NN + n0 + tx];
    }
    __syncthreads();
#pragma unroll
    for (int i = 0; i < 4; i++) {
        int n = n0 + ty + i * 8;
        ob[(size_t)n * CC + c0 + tx] = tile[tx][ty + i * 8];
    }
}

// ---------------- Kernel 1: KNN + MLP + normalize + proj -> projL ----------------
// Dynamic smem layout:
//   sx[N], sy[N], sz[N]                (48 KB)
//   sW[448]                            (MLP weights)
//   cand[NWARP][CAP]  (uint64)         (20 KB)
//   swf [NWARP][512]  ([k*32+s])       (16 KB)
//   sf  [NWARP][32*68] ([s*68+c])      (68 KB)   (also reused as proj staging)
#define SMEM_SW_OFF   (3 * NN)
#define SMEM_CAND_OFF (3 * NN + 448)
#define SMEM1_BYTES   (size_t)( (3*NN + 448) * 4 + NWARP * CAP * 8 + NWARP * 512 * 4 + NWARP * 32 * 68 * 4 )

__global__ __launch_bounds__(256, 1) void main_kernel(
    const float* __restrict__ xyz,
    const float* __restrict__ W1, const float* __restrict__ b1,
    const float* __restrict__ W2, const float* __restrict__ b2,
    const float* __restrict__ W3, const float* __restrict__ b3)
{
    extern __shared__ char smem_raw[];
    float* sx = (float*)smem_raw;
    float* sy = sx + NN;
    float* sz = sy + NN;
    float* sW = sx + SMEM_SW_OFF;
    unsigned long long* candAll = (unsigned long long*)(sx + SMEM_CAND_OFF);
    float* swfAll = (float*)(candAll + NWARP * CAP);
    float* sfAll  = swfAll + NWARP * 512;

    int b   = blockIdx.y;
    int tid = threadIdx.x;
    int w = tid >> 5, lane = tid & 31;
    unsigned long long* cand = candAll + w * CAP;
    float* swf = swfAll + w * 512;
    float* sf  = sfAll  + (size_t)w * (32 * 68);

    // load batch xyz into smem (SoA)
    const float* xb = xyz + (size_t)b * NN * 3;
    for (int i = tid; i < NN; i += 256) {
        sx[i] = xb[i * 3 + 0];
        sy[i] = xb[i * 3 + 1];
        sz[i] = xb[i * 3 + 2];
    }
    // load MLP weights: [0..23] W1, [24..31] b1, [32..159] W2, [160..175] b2, [176..431] W3, [432..447] b3
    if (tid < 24)  sW[tid] = W1[tid];
    if (tid < 8)   sW[24 + tid] = b1[tid];
    if (tid < 128) sW[32 + tid] = W2[tid];
    if (tid < 16)  sW[160 + tid] = b2[tid];
    sW[176 + tid] = W3[tid];          // 256 values, 256 threads
    if (tid < 16)  sW[432 + tid] = b3[tid];
    __syncthreads();

    const float* fT = g_featT + (size_t)b * NN * CC;
    float* projBase = g_projL + (size_t)b * NN * 1024;
    int nbase = blockIdx.x * CPB;

    for (int ci = w; ci < CPB; ci += NWARP) {
        int n = nbase + ci;
        float cx = sx[n], cy = sy[n], cz = sz[n];

        // ---- radius scan over all N points ----
        int cnt = 0;
        for (int j = lane; j < NN; j += 32) {
            float dx = sx[j] - cx, dy = sy[j] - cy, dz = sz[j] - cz;
            float d2 = dx * dx + dy * dy + dz * dz;
            bool in = (d2 <= R2C);
            unsigned m = __ballot_sync(0xffffffffu, in);
            if (in) {
                int pos = cnt + __popc(m & ((1u << lane) - 1u));
                if (pos < CAP)
                    cand[pos] = ((unsigned long long)__float_as_uint(d2) << 32) | (unsigned)j;
            }
            cnt += __popc(m);
        }
        int M = min(cnt, CAP);
        __syncwarp();

        // ---- pick 32 nearest (or pad with self) ----
        unsigned long long mykey;
        if (M <= NS) {
            mykey = (lane < M) ? cand[lane] : (unsigned long long)(unsigned)n;  // self: d2 bits = 0
        } else {
            mykey = 0;
            for (int r = 0; r < NS; r++) {
                unsigned long long lmin = ~0ull; int lpos = 0;
                for (int p = lane; p < M; p += 32) {
                    unsigned long long k = cand[p];
                    if (k < lmin) { lmin = k; lpos = p; }
                }
#pragma unroll
                for (int off = 16; off; off >>= 1) {
                    unsigned long long ok = __shfl_xor_sync(0xffffffffu, lmin, off);
                    int op = __shfl_xor_sync(0xffffffffu, lpos, off);
                    if (ok < lmin) { lmin = ok; lpos = op; }
                }
                if (lane == r) mykey = lmin;
                if (lane == 0) cand[lpos] = ~0ull;
                __syncwarp();
            }
        }
        int nj = (int)(mykey & 0xffffffffu);
        float gx = sx[nj] - cx, gy = sy[nj] - cy, gz = sz[nj] - cz;

        // ---- MLP 3 -> 8 -> 16 -> 16 ----
        float h1[8];
#pragma unroll
        for (int o = 0; o < 8; o++)
            h1[o] = leaky(sW[o * 3 + 0] * gx + sW[o * 3 + 1] * gy + sW[o * 3 + 2] * gz + sW[24 + o]);
        float h2[16];
#pragma unroll
        for (int o = 0; o < 16; o++) {
            float a = sW[160 + o];
#pragma unroll
            for (int i = 0; i < 8; i++) a += sW[32 + o * 8 + i] * h1[i];
            h2[o] = leaky(a);
        }
        float wv[16]; float w2sum = 0.0f;
#pragma unroll
        for (int o = 0; o < 16; o++) {
            float a = sW[432 + o];
#pragma unroll
            for (int i = 0; i < 16; i++) a += sW[176 + o * 16 + i] * h2[i];
            wv[o] = a; w2sum += a * a;
        }
        float inv1 = 1.0f / sqrtf(fmaxf(w2sum, 1e-8f));

        // s2 per k: warp-sum of original squares over the 32 slots
        float inv2[16];
#pragma unroll
        for (int k = 0; k < 16; k++) {
            float t = wv[k] * wv[k];
#pragma unroll
            for (int off = 16; off; off >>= 1) t += __shfl_xor_sync(0xffffffffu, t, off);
            inv2[k] = 1.0f / fmaxf(sqrtf(fmaxf(t, 1e-8f)), 1.0f);
        }

        // store normalized weights: swf[k*32+s]
#pragma unroll
        for (int k = 0; k < 16; k++) swf[k * 32 + lane] = wv[k] * inv1 * inv2[k];

        // gather neighbor feature row (contiguous 256B from featT)
        const float4* frow = (const float4*)(fT + (size_t)nj * CC);
#pragma unroll
        for (int c4 = 0; c4 < 16; c4++) {
            float4 v = frow[c4];
            *(float4*)&sf[lane * 68 + c4 * 4] = v;
        }
        __syncwarp();

        // ---- proj[k][c] = sum_s wf[s][k] * f[s][c]; lane owns channels 2*lane, 2*lane+1 ----
        float acc0[16], acc1[16];
#pragma unroll
        for (int k = 0; k < 16; k++) { acc0[k] = 0.0f; acc1[k] = 0.0f; }
        for (int s = 0; s < 32; s++) {
            float2 f = *(const float2*)&sf[s * 68 + 2 * lane];
#pragma unroll
            for (int k = 0; k < 16; k++) {
                float wk = swf[k * 32 + s];   // smem broadcast
                acc0[k] += wk * f.x;
                acc1[k] += wk * f.y;
            }
        }
        __syncwarp();
        // stage leaky(proj) into smem in final layout c*16+k, then coalesced write
#pragma unroll
        for (int k = 0; k < 16; k++) {
            sf[(2 * lane) * 16 + k]     = leaky(acc0[k]);
            sf[(2 * lane + 1) * 16 + k] = leaky(acc1[k]);
        }
        __syncwarp();
        float4* orow = (float4*)(projBase + (size_t)n * 1024);
        const float4* srow = (const float4*)sf;
#pragma unroll
        for (int i = 0; i < 8; i++) orow[lane + i * 32] = srow[lane + i * 32];
        __syncwarp();
    }
}

// ---------------- Kernel 2: out[b,o,n] = leaky(Wc[o,:] . projL[bn,:] + bc[o]) ----------------
#define NT 128
__global__ __launch_bounds__(256) void gemm_kernel(
    const float* __restrict__ Wc, const float* __restrict__ bc, float* __restrict__ out)
{
    __shared__ float sA[32][64];        // [kk][o]
    __shared__ float sB[32][NT + 4];    // [kk][n]
    int tid = threadIdx.x;
    size_t row0 = (size_t)blockIdx.x * NT;
    int b  = (int)(row0 >> 12);
    int n0 = (int)(row0 & 4095);
    int o_base = (tid >> 4) * 4;
    int n_base = (tid & 15) * 8;
    float acc[4][8];
#pragma unroll
    for (int i = 0; i < 4; i++)
#pragma unroll
        for (int j = 0; j < 8; j++) acc[i][j] = 0.0f;

    const float* pB = g_projL + row0 * 1024;
    for (int k0 = 0; k0 < 1024; k0 += 32) {
        // load A chunk: Wc[o][k0+kk] -> sA[kk][o]
        {
            int o = tid >> 2, kk = (tid & 3) * 8;
            const float4* src = (const float4*)(Wc + (size_t)o * 1024 + k0 + kk);
            float4 v0 = src[0], v1 = src[1];
            sA[kk + 0][o] = v0.x; sA[kk + 1][o] = v0.y; sA[kk + 2][o] = v0.z; sA[kk + 3][o] = v0.w;
            sA[kk + 4][o] = v1.x; sA[kk + 5][o] = v1.y; sA[kk + 6][o] = v1.z; sA[kk + 7][o] = v1.w;
        }
        // load B chunk: projL[row0+r][k0+kk] -> sB[kk][r]
        {
            int r = tid >> 1, kk = (tid & 1) * 16;
            const float4* src = (const float4*)(pB + (size_t)r * 1024 + k0 + kk);
#pragma unroll
            for (int q = 0; q < 4; q++) {
                float4 v = src[q];
                sB[kk + q * 4 + 0][r] = v.x; sB[kk + q * 4 + 1][r] = v.y;
                sB[kk + q * 4 + 2][r] = v.z; sB[kk + q * 4 + 3][r] = v.w;
            }
        }
        __syncthreads();
#pragma unroll
        for (int kk = 0; kk < 32; kk++) {
            float4 a  = *(const float4*)&sA[kk][o_base];
            float4 b0 = *(const float4*)&sB[kk][n_base];
            float4 b1 = *(const float4*)&sB[kk][n_base + 4];
            float av[4] = {a.x, a.y, a.z, a.w};
            float bv[8] = {b0.x, b0.y, b0.z, b0.w, b1.x, b1.y, b1.z, b1.w};
#pragma unroll
            for (int i = 0; i < 4; i++)
#pragma unroll
                for (int j = 0; j < 8; j++) acc[i][j] += av[i] * bv[j];
        }
        __syncthreads();
    }
    // epilogue
#pragma unroll
    for (int i = 0; i < 4; i++) {
        float bias = __ldg(&bc[o_base + i]);
        float* orow = out + (size_t)b * OUTC * NN + (size_t)(o_base + i) * NN + n0 + n_base;
        float4 v0, v1;
        v0.x = leaky(acc[i][0] + bias); v0.y = leaky(acc[i][1] + bias);
        v0.z = leaky(acc[i][2] + bias); v0.w = leaky(acc[i][3] + bias);
        v1.x = leaky(acc[i][4] + bias); v1.y = leaky(acc[i][5] + bias);
        v1.z = leaky(acc[i][6] + bias); v1.w = leaky(acc[i][7] + bias);
        *(float4*)&orow[0] = v0;
        *(float4*)&orow[4] = v1;
    }
}

extern "C" void kernel_launch(void* const* d_in, const int* in_sizes, int n_in,
                              void* d_out, int out_size) {
    const float* xyz  = (const float*)d_in[0];
    const float* feat = (const float*)d_in[1];
    const float* W1 = (const float*)d_in[2];
    const float* b1 = (const float*)d_in[3];
    const float* W2 = (const float*)d_in[4];
    const float* b2 = (const float*)d_in[5];
    const float* W3 = (const float*)d_in[6];
    const float* b3 = (const float*)d_in[7];
    const float* Wc = (const float*)d_in[8];
    const float* bc = (const float*)d_in[9];

    float* out = (float*)d_out;
    float* out_main = out;
    const int xyz_elems = BB * NN * 3;
    const int out_elems = BB * OUTC * NN;
    if (out_size == xyz_elems + out_elems) {
        // reference returns (xyz, out): xyz passthrough first
        cudaMemcpyAsync(out, xyz, (size_t)xyz_elems * sizeof(float), cudaMemcpyDeviceToDevice);
        out_main = out + xyz_elems;
    }

    transpose_kernel<<<dim3(NN / 32, CC / 32, BB), dim3(32, 8)>>>(feat);

    cudaFuncSetAttribute(main_kernel, cudaFuncAttributeMaxDynamicSharedMemorySize, (int)SMEM1_BYTES);
    main_kernel<<<dim3(NN / CPB, BB), 256, SMEM1_BYTES>>>(xyz, W1, b1, W2, b2, W3, b3);

    gemm_kernel<<<(BB * NN) / NT, 256>>>(Wc, bc, out_main);
}

// round 2
// speedup vs baseline: 1.9118x; 1.9118x over previous
#include <cuda_runtime.h>
#include <cstdint>

#define BB 8
#define NN 4096
#define CC 64
#define OUTC 64
#define NS 32
#define R2C 0.04f
#define ALPHA 0.2f
#define CAPK 224

// ---- device scratch (allocation-free rule) ----
__device__ float g_featT[(size_t)BB * NN * CC];        // (B,N,C) 8 MB
__device__ float g_projL[(size_t)BB * NN * 16 * CC];   // 134 MB, k-major rows: [k*64+c]
__device__ float g_WcP[(size_t)OUTC * 16 * CC];        // Wc permuted to k-major
__device__ int   g_idx[(size_t)BB * NN * NS];
__device__ float g_gx [(size_t)BB * NN * NS];
__device__ float g_gy [(size_t)BB * NN * NS];
__device__ float g_gz [(size_t)BB * NN * NS];

__device__ __forceinline__ float leaky(float x) { return fmaxf(x, ALPHA * x); }

// ---------------- transpose: (B,C,N) -> (B,N,C) ----------------
__global__ void transpose_kernel(const float* __restrict__ feat) {
    __shared__ float tile[32][33];
    int b = blockIdx.z, n0 = blockIdx.x * 32, c0 = blockIdx.y * 32;
    int tx = threadIdx.x, ty = threadIdx.y;
    const float* fb = feat + (size_t)b * CC * NN;
    float* ob = g_featT + (size_t)b * NN * CC;
#pragma unroll
    for (int i = 0; i < 4; i++)
        tile[ty + i * 8][tx] = fb[(size_t)(c0 + ty + i * 8) * NN + n0 + tx];
    __syncthreads();
#pragma unroll
    for (int i = 0; i < 4; i++)
        ob[(size_t)(n0 + ty + i * 8) * CC + c0 + tx] = tile[tx][ty + i * 8];
}

// ---------------- Wc permute: WcP[o][k*64+c] = Wc[o][c*16+k] ----------------
__global__ void wcperm_kernel(const float* __restrict__ Wc) {
    int idx = blockIdx.x * 256 + threadIdx.x;   // 65536
    int o = idx >> 10, r = idx & 1023, k = r >> 6, c = r & 63;
    g_WcP[idx] = Wc[o * 1024 + c * 16 + k];
}

// ---------------- KNN: radius scan + rank selection ----------------
// smem: sx,sy,sz[4096] (48KB) + cand u64 [8 warps][4 centers][CAPK] (56KB)
#define KNN_SMEM (size_t)(3 * NN * 4 + 8 * 4 * CAPK * 8)

__global__ __launch_bounds__(256, 2) void knn_kernel(const float* __restrict__ xyz) {
    extern __shared__ char smem_raw[];
    float* sx = (float*)smem_raw;
    float* sy = sx + NN;
    float* sz = sy + NN;
    unsigned long long* candAll = (unsigned long long*)(sz + NN);

    int b = blockIdx.y, tid = threadIdx.x, w = tid >> 5, lane = tid & 31;
    const float* xb = xyz + (size_t)b * NN * 3;
    for (int i = tid; i < NN; i += 256) {
        sx[i] = xb[i * 3 + 0];
        sy[i] = xb[i * 3 + 1];
        sz[i] = xb[i * 3 + 2];
    }
    __syncthreads();

    int nbase = blockIdx.x * 32 + w * 4;
    unsigned long long* cand0 = candAll + (size_t)w * 4 * CAPK;
    float cx[4], cy[4], cz[4];
    int cnt[4];
#pragma unroll
    for (int i = 0; i < 4; i++) {
        cx[i] = sx[nbase + i]; cy[i] = sy[nbase + i]; cz[i] = sz[nbase + i];
        cnt[i] = 0;
    }
    unsigned lmask = (1u << lane) - 1u;

    for (int j = lane; j < NN; j += 32) {
        float px = sx[j], py = sy[j], pz = sz[j];
#pragma unroll
        for (int i = 0; i < 4; i++) {
            float dx = px - cx[i], dy = py - cy[i], dz = pz - cz[i];
            float d2 = fmaf(dx, dx, fmaf(dy, dy, dz * dz));
            bool in = (d2 <= R2C);
            unsigned m = __ballot_sync(0xffffffffu, in);
            if (in) {
                int pos = cnt[i] + __popc(m & lmask);
                if (pos < CAPK)
                    cand0[i * CAPK + pos] =
                        ((unsigned long long)__float_as_uint(d2) << 32) | (unsigned)j;
            }
            cnt[i] += __popc(m);
        }
    }
    __syncwarp();

#pragma unroll
    for (int i = 0; i < 4; i++) {
        int n = nbase + i;
        size_t cg = (size_t)b * NN + n;
        int M = min(cnt[i], CAPK);
        const unsigned long long* cd = cand0 + i * CAPK;

        // slots >= M get self (gxyz = 0)
        if (lane >= M) {
            g_idx[cg * NS + lane] = n;
            g_gx[cg * NS + lane] = 0.0f;
            g_gy[cg * NS + lane] = 0.0f;
            g_gz[cg * NS + lane] = 0.0f;
        }

        // load my candidates (<=7) into regs
        unsigned long long k[7];
        int r[7];
#pragma unroll
        for (int t = 0; t < 7; t++) {
            int p = lane + 32 * t;
            k[t] = (p < M) ? cd[p] : ~0ull;
            r[t] = 0;
        }
        // rank pass: broadcast each key, count strictly-smaller
        for (int q = 0; q < M; q++) {
            unsigned long long kq = cd[q];
#pragma unroll
            for (int t = 0; t < 7; t++) r[t] += (kq < k[t]);
        }
        // scatter top-32 by rank
#pragma unroll
        for (int t = 0; t < 7; t++) {
            int p = lane + 32 * t;
            if (p < M && r[t] < NS) {
                int jj = (int)(k[t] & 0xffffffffull);
                g_idx[cg * NS + r[t]] = jj;
                g_gx[cg * NS + r[t]] = sx[jj] - cx[i];
                g_gy[cg * NS + r[t]] = sy[jj] - cy[i];
                g_gz[cg * NS + r[t]] = sz[jj] - cz[i];
            }
        }
        __syncwarp();
    }
}

// ---------------- projgen: MLP + normalize + rank-32 proj ----------------
#define CW 4   // centers per warp
__global__ __launch_bounds__(256) void projgen_kernel(
    const float* __restrict__ W1, const float* __restrict__ b1,
    const float* __restrict__ W2, const float* __restrict__ b2,
    const float* __restrict__ W3, const float* __restrict__ b3)
{
    __shared__ float swfAll[8][512];   // per warp: [quad][slot] float4-packed weights
    __shared__ int   snjAll[8][32];
    __shared__ float sW[448];

    int tid = threadIdx.x, w = tid >> 5, lane = tid & 31;
    if (tid < 24)  sW[tid] = W1[tid];
    if (tid < 8)   sW[24 + tid] = b1[tid];
    if (tid < 128) sW[32 + tid] = W2[tid];
    if (tid < 16)  sW[160 + tid] = b2[tid];
    sW[176 + tid] = W3[tid];
    if (tid < 16)  sW[432 + tid] = b3[tid];
    __syncthreads();

    float* swf = swfAll[w];
    int* snj = snjAll[w];

    for (int it = 0; it < CW; it++) {
        size_t cg = (size_t)blockIdx.x * (8 * CW) + w * CW + it;  // global center
        int bb = (int)(cg >> 12);

        int   nj = g_idx[cg * NS + lane];
        float gx = g_gx[cg * NS + lane];
        float gy = g_gy[cg * NS + lane];
        float gz = g_gz[cg * NS + lane];

        // MLP 3->8->16->16
        float h1[8];
#pragma unroll
        for (int o = 0; o < 8; o++)
            h1[o] = leaky(fmaf(sW[o*3+0], gx, fmaf(sW[o*3+1], gy, fmaf(sW[o*3+2], gz, sW[24+o]))));
        float h2[16];
#pragma unroll
        for (int o = 0; o < 16; o++) {
            float a = sW[160 + o];
#pragma unroll
            for (int i = 0; i < 8; i++) a = fmaf(sW[32 + o*8 + i], h1[i], a);
            h2[o] = leaky(a);
        }
        float wv[16], w2sum = 0.0f;
#pragma unroll
        for (int o = 0; o < 16; o++) {
            float a = sW[432 + o];
#pragma unroll
            for (int i = 0; i < 16; i++) a = fmaf(sW[176 + o*16 + i], h2[i], a);
            wv[o] = a; w2sum = fmaf(a, a, w2sum);
        }
        float inv1 = rsqrtf(fmaxf(w2sum, 1e-8f));

        // s2 per k over slots (warp allreduce of original squares), then combine
        float wn[16];
#pragma unroll
        for (int kk = 0; kk < 16; kk++) {
            float t = wv[kk] * wv[kk];
#pragma unroll
            for (int off = 16; off; off >>= 1) t += __shfl_xor_sync(0xffffffffu, t, off);
            float s2 = fmaxf(sqrtf(fmaxf(t, 1e-8f)), 1.0f);
            wn[kk] = wv[kk] * inv1 * (1.0f / s2);
        }

        // stage weights: swf4[q*32 + s] = quad q of lane s  (conflict-free)
        float4* swf4 = (float4*)swf;
#pragma unroll
        for (int q = 0; q < 4; q++)
            swf4[q * 32 + lane] = make_float4(wn[4*q], wn[4*q+1], wn[4*q+2], wn[4*q+3]);
        snj[lane] = nj;
        __syncwarp();

        // proj: lane owns channels 2*lane, 2*lane+1
        const float* fT = g_featT + (size_t)bb * NN * CC;
        float2 buf[8];
#pragma unroll
        for (int p = 0; p < 8; p++)
            buf[p] = *(const float2*)(fT + (size_t)snj[p] * CC + 2 * lane);

        float acc0[16], acc1[16];
#pragma unroll
        for (int kk = 0; kk < 16; kk++) { acc0[kk] = 0.0f; acc1[kk] = 0.0f; }

#pragma unroll
        for (int s = 0; s < 32; s++) {
            float2 f = buf[s & 7];
            if (s < 24)
                buf[s & 7] = *(const float2*)(fT + (size_t)snj[s + 8] * CC + 2 * lane);
            float4 q0 = swf4[s], q1 = swf4[32 + s], q2 = swf4[64 + s], q3 = swf4[96 + s];
            acc0[0]  = fmaf(q0.x, f.x, acc0[0]);  acc1[0]  = fmaf(q0.x, f.y, acc1[0]);
            acc0[1]  = fmaf(q0.y, f.x, acc0[1]);  acc1[1]  = fmaf(q0.y, f.y, acc1[1]);
            acc0[2]  = fmaf(q0.z, f.x, acc0[2]);  acc1[2]  = fmaf(q0.z, f.y, acc1[2]);
            acc0[3]  = fmaf(q0.w, f.x, acc0[3]);  acc1[3]  = fmaf(q0.w, f.y, acc1[3]);
            acc0[4]  = fmaf(q1.x, f.x, acc0[4]);  acc1[4]  = fmaf(q1.x, f.y, acc1[4]);
            acc0[5]  = fmaf(q1.y, f.x, acc0[5]);  acc1[5]  = fmaf(q1.y, f.y, acc1[5]);
            acc0[6]  = fmaf(q1.z, f.x, acc0[6]);  acc1[6]  = fmaf(q1.z, f.y, acc1[6]);
            acc0[7]  = fmaf(q1.w, f.x, acc0[7]);  acc1[7]  = fmaf(q1.w, f.y, acc1[7]);
            acc0[8]  = fmaf(q2.x, f.x, acc0[8]);  acc1[8]  = fmaf(q2.x, f.y, acc1[8]);
            acc0[9]  = fmaf(q2.y, f.x, acc0[9]);  acc1[9]  = fmaf(q2.y, f.y, acc1[9]);
            acc0[10] = fmaf(q2.z, f.x, acc0[10]); acc1[10] = fmaf(q2.z, f.y, acc1[10]);
            acc0[11] = fmaf(q2.w, f.x, acc0[11]); acc1[11] = fmaf(q2.w, f.y, acc1[11]);
            acc0[12] = fmaf(q3.x, f.x, acc0[12]); acc1[12] = fmaf(q3.x, f.y, acc1[12]);
            acc0[13] = fmaf(q3.y, f.x, acc0[13]); acc1[13] = fmaf(q3.y, f.y, acc1[13]);
            acc0[14] = fmaf(q3.z, f.x, acc0[14]); acc1[14] = fmaf(q3.z, f.y, acc1[14]);
            acc0[15] = fmaf(q3.w, f.x, acc0[15]); acc1[15] = fmaf(q3.w, f.y, acc1[15]);
        }

        // write k-major: projL[cg][k*64 + c], c = 2*lane (coalesced 256B STG64s)
        float* orow = g_projL + cg * 1024;
#pragma unroll
        for (int kk = 0; kk < 16; kk++)
            *(float2*)(orow + kk * 64 + 2 * lane) =
                make_float2(leaky(acc0[kk]), leaky(acc1[kk]));
        __syncwarp();
    }
}

// ---------------- GEMM: out[b,o,n] = leaky(WcP[o,:] . projL[bn,:] + bc[o]) ----------------
#define NT 64
__global__ __launch_bounds__(256) void gemm_kernel(const float* __restrict__ bc,
                                                   float* __restrict__ out)
{
    __shared__ float sA[32][68];   // [kk][o]
    __shared__ float sB[32][68];   // [kk][n]
    int tid = threadIdx.x;
    size_t row0 = (size_t)blockIdx.x * NT;
    int b  = (int)(row0 >> 12);
    int n0 = (int)(row0 & 4095);
    int o_base = (tid >> 4) * 4;
    int n_base = (tid & 15) * 4;
    float acc[4][4];
#pragma unroll
    for (int i = 0; i < 4; i++)
#pragma unroll
        for (int j = 0; j < 4; j++) acc[i][j] = 0.0f;

    const float* pB = g_projL + row0 * 1024;
    int lr = tid >> 2, lk = (tid & 3) * 8;

    for (int k0 = 0; k0 < 1024; k0 += 32) {
        {   // A: WcP[o][k0+kk] -> sA[kk][o]
            const float4* src = (const float4*)(g_WcP + (size_t)lr * 1024 + k0 + lk);
            float4 v0 = src[0], v1 = src[1];
            sA[lk + 0][lr] = v0.x; sA[lk + 1][lr] = v0.y; sA[lk + 2][lr] = v0.z; sA[lk + 3][lr] = v0.w;
            sA[lk + 4][lr] = v1.x; sA[lk + 5][lr] = v1.y; sA[lk + 6][lr] = v1.z; sA[lk + 7][lr] = v1.w;
        }
        {   // B: projL[row0+r][k0+kk] -> sB[kk][r]   (r = lr & 63)
            int r = lr & 63;
            const float4* src = (const float4*)(pB + (size_t)r * 1024 + ((lr & 64) ? 16 : 0) + k0 + lk);
            // lr in [0,64): handles all rows once; lr>=64 impossible (tid<256 -> lr<64). plain:
            (void)src;
        }
        {   // B load: 256 threads, 64 rows x 32 kk -> each thread 8 elems
            int r = tid >> 2;  // 0..63
            const float4* src = (const float4*)(pB + (size_t)r * 1024 + k0 + lk);
            float4 v0 = src[0], v1 = src[1];
            sB[lk + 0][r] = v0.x; sB[lk + 1][r] = v0.y; sB[lk + 2][r] = v0.z; sB[lk + 3][r] = v0.w;
            sB[lk + 4][r] = v1.x; sB[lk + 5][r] = v1.y; sB[lk + 6][r] = v1.z; sB[lk + 7][r] = v1.w;
        }
        __syncthreads();
#pragma unroll
        for (int kk = 0; kk < 32; kk++) {
            float4 a = *(const float4*)&sA[kk][o_base];
            float4 bq = *(const float4*)&sB[kk][n_base];
            float av[4] = {a.x, a.y, a.z, a.w};
            float bv[4] = {bq.x, bq.y, bq.z, bq.w};
#pragma unroll
            for (int i = 0; i < 4; i++)
#pragma unroll
                for (int j = 0; j < 4; j++) acc[i][j] = fmaf(av[i], bv[j], acc[i][j]);
        }
        __syncthreads();
    }
#pragma unroll
    for (int i = 0; i < 4; i++) {
        float bias = __ldg(&bc[o_base + i]);
        float* orow = out + (size_t)b * OUTC * NN + (size_t)(o_base + i) * NN + n0 + n_base;
        float4 v;
        v.x = leaky(acc[i][0] + bias); v.y = leaky(acc[i][1] + bias);
        v.z = leaky(acc[i][2] + bias); v.w = leaky(acc[i][3] + bias);
        *(float4*)orow = v;
    }
}

extern "C" void kernel_launch(void* const* d_in, const int* in_sizes, int n_in,
                              void* d_out, int out_size) {
    const float* xyz  = (const float*)d_in[0];
    const float* feat = (const float*)d_in[1];
    const float* W1 = (const float*)d_in[2];
    const float* b1 = (const float*)d_in[3];
    const float* W2 = (const float*)d_in[4];
    const float* b2 = (const float*)d_in[5];
    const float* W3 = (const float*)d_in[6];
    const float* b3 = (const float*)d_in[7];
    const float* Wc = (const float*)d_in[8];
    const float* bc = (const float*)d_in[9];

    float* out = (float*)d_out;
    float* out_main = out;
    const int xyz_elems = BB * NN * 3;
    const int out_elems = BB * OUTC * NN;
    if (out_size == xyz_elems + out_elems) {
        cudaMemcpyAsync(out, xyz, (size_t)xyz_elems * sizeof(float), cudaMemcpyDeviceToDevice);
        out_main = out + xyz_elems;
    }

    transpose_kernel<<<dim3(NN / 32, CC / 32, BB), dim3(32, 8)>>>(feat);
    wcperm_kernel<<<(OUTC * 1024) / 256, 256>>>(Wc);

    cudaFuncSetAttribute(knn_kernel, cudaFuncAttributeMaxDynamicSharedMemorySize, (int)KNN_SMEM);
    knn_kernel<<<dim3(NN / 32, BB), 256, KNN_SMEM>>>(xyz);

    projgen_kernel<<<(BB * NN) / (8 * CW), 256>>>(W1, b1, W2, b2, W3, b3);

    gemm_kernel<<<(BB * NN) / NT, 256>>>(bc, out_main);
}

// round 3
// speedup vs baseline: 2.2399x; 1.1716x over previous
#include <cuda_runtime.h>
#include <cstdint>

#define BB 8
#define NN 4096
#define CC 64
#define OUTC 64
#define NS 32
#define R2C 0.04f
#define ALPHA 0.2f
#define CAPK 224

// ---- device scratch (allocation-free rule) ----
__device__ float g_featT[(size_t)BB * NN * CC];        // (B,N,C) 8 MB
__device__ float g_projL[(size_t)BB * NN * 16 * CC];   // 134 MB, k-major rows
__device__ float g_WcP[(size_t)OUTC * 16 * CC];        // Wc permuted to k-major
__device__ int   g_idx[(size_t)BB * NN * NS];
__device__ float g_gx [(size_t)BB * NN * NS];
__device__ float g_gy [(size_t)BB * NN * NS];
__device__ float g_gz [(size_t)BB * NN * NS];

__device__ __forceinline__ float leaky(float x) { return fmaxf(x, ALPHA * x); }

__device__ __forceinline__ void tf32split(float x, uint32_t& hi, uint32_t& lo) {
    uint32_t h;
    asm("cvt.rna.tf32.f32 %0, %1;" : "=r"(h) : "f"(x));
    hi = h;
    lo = __float_as_uint(x - __uint_as_float(h));
}

__device__ __forceinline__ void mma_tf32(float* c, const uint32_t* a, const uint32_t* b) {
    asm volatile(
        "mma.sync.aligned.m16n8k8.row.col.f32.tf32.tf32.f32 "
        "{%0,%1,%2,%3}, {%4,%5,%6,%7}, {%8,%9}, {%0,%1,%2,%3};"
        : "+f"(c[0]), "+f"(c[1]), "+f"(c[2]), "+f"(c[3])
        : "r"(a[0]), "r"(a[1]), "r"(a[2]), "r"(a[3]), "r"(b[0]), "r"(b[1]));
}

// ---------------- transpose: (B,C,N) -> (B,N,C) ----------------
__global__ void transpose_kernel(const float* __restrict__ feat) {
    __shared__ float tile[32][33];
    int b = blockIdx.z, n0 = blockIdx.x * 32, c0 = blockIdx.y * 32;
    int tx = threadIdx.x, ty = threadIdx.y;
    const float* fb = feat + (size_t)b * CC * NN;
    float* ob = g_featT + (size_t)b * NN * CC;
#pragma unroll
    for (int i = 0; i < 4; i++)
        tile[ty + i * 8][tx] = fb[(size_t)(c0 + ty + i * 8) * NN + n0 + tx];
    __syncthreads();
#pragma unroll
    for (int i = 0; i < 4; i++)
        ob[(size_t)(n0 + ty + i * 8) * CC + c0 + tx] = tile[tx][ty + i * 8];
}

// ---------------- Wc permute: WcP[o][k*64+c] = Wc[o][c*16+k] ----------------
__global__ void wcperm_kernel(const float* __restrict__ Wc) {
    int idx = blockIdx.x * 256 + threadIdx.x;   // 65536
    int o = idx >> 10, r = idx & 1023, k = r >> 6, c = r & 63;
    g_WcP[idx] = Wc[o * 1024 + c * 16 + k];
}

// ---------------- KNN: radius scan + rank selection ----------------
#define KNN_SMEM (size_t)(3 * NN * 4 + 8 * 4 * CAPK * 8)

__global__ __launch_bounds__(256, 2) void knn_kernel(const float* __restrict__ xyz) {
    extern __shared__ char smem_raw[];
    float* sx = (float*)smem_raw;
    float* sy = sx + NN;
    float* sz = sy + NN;
    unsigned long long* candAll = (unsigned long long*)(sz + NN);

    int b = blockIdx.y, tid = threadIdx.x, w = tid >> 5, lane = tid & 31;
    const float* xb = xyz + (size_t)b * NN * 3;
    for (int i = tid; i < NN; i += 256) {
        sx[i] = xb[i * 3 + 0];
        sy[i] = xb[i * 3 + 1];
        sz[i] = xb[i * 3 + 2];
    }
    __syncthreads();

    int nbase = blockIdx.x * 32 + w * 4;
    unsigned long long* cand0 = candAll + (size_t)w * 4 * CAPK;
    float cx[4], cy[4], cz[4];
    int cnt[4];
#pragma unroll
    for (int i = 0; i < 4; i++) {
        cx[i] = sx[nbase + i]; cy[i] = sy[nbase + i]; cz[i] = sz[nbase + i];
        cnt[i] = 0;
    }
    unsigned lmask = (1u << lane) - 1u;

    for (int j = lane; j < NN; j += 32) {
        float px = sx[j], py = sy[j], pz = sz[j];
#pragma unroll
        for (int i = 0; i < 4; i++) {
            float dx = px - cx[i], dy = py - cy[i], dz = pz - cz[i];
            float d2 = fmaf(dx, dx, fmaf(dy, dy, dz * dz));
            bool in = (d2 <= R2C);
            unsigned m = __ballot_sync(0xffffffffu, in);
            if (in) {
                int pos = cnt[i] + __popc(m & lmask);
                if (pos < CAPK)
                    cand0[i * CAPK + pos] =
                        ((unsigned long long)__float_as_uint(d2) << 32) | (unsigned)j;
            }
            cnt[i] += __popc(m);
        }
    }
    __syncwarp();

#pragma unroll
    for (int i = 0; i < 4; i++) {
        int n = nbase + i;
        size_t cg = (size_t)b * NN + n;
        int M = min(cnt[i], CAPK);
        const unsigned long long* cd = cand0 + i * CAPK;

        if (lane >= M) {
            g_idx[cg * NS + lane] = n;
            g_gx[cg * NS + lane] = 0.0f;
            g_gy[cg * NS + lane] = 0.0f;
            g_gz[cg * NS + lane] = 0.0f;
        }
        unsigned long long k[7];
        int r[7];
#pragma unroll
        for (int t = 0; t < 7; t++) {
            int p = lane + 32 * t;
            k[t] = (p < M) ? cd[p] : ~0ull;
            r[t] = 0;
        }
        for (int q = 0; q < M; q++) {
            unsigned long long kq = cd[q];
#pragma unroll
            for (int t = 0; t < 7; t++) r[t] += (kq < k[t]);
        }
#pragma unroll
        for (int t = 0; t < 7; t++) {
            int p = lane + 32 * t;
            if (p < M && r[t] < NS) {
                int jj = (int)(k[t] & 0xffffffffull);
                g_idx[cg * NS + r[t]] = jj;
                g_gx[cg * NS + r[t]] = sx[jj] - cx[i];
                g_gy[cg * NS + r[t]] = sy[jj] - cy[i];
                g_gz[cg * NS + r[t]] = sz[jj] - cz[i];
            }
        }
        __syncwarp();
    }
}

// ---------------- projgen: MLP + normalize + rank-32 proj ----------------
#define CW 2   // centers per warp
__global__ __launch_bounds__(256) void projgen_kernel(
    const float* __restrict__ W1, const float* __restrict__ b1,
    const float* __restrict__ W2, const float* __restrict__ b2,
    const float* __restrict__ W3, const float* __restrict__ b3)
{
    __shared__ float swfAll[8][512];
    __shared__ int   snjAll[8][32];
    __shared__ float sW[448];

    int tid = threadIdx.x, w = tid >> 5, lane = tid & 31;
    if (tid < 24)  sW[tid] = W1[tid];
    if (tid < 8)   sW[24 + tid] = b1[tid];
    if (tid < 128) sW[32 + tid] = W2[tid];
    if (tid < 16)  sW[160 + tid] = b2[tid];
    sW[176 + tid] = W3[tid];
    if (tid < 16)  sW[432 + tid] = b3[tid];
    __syncthreads();

    float* swf = swfAll[w];
    int* snj = snjAll[w];

    for (int it = 0; it < CW; it++) {
        size_t cg = (size_t)blockIdx.x * (8 * CW) + w * CW + it;
        int bb = (int)(cg >> 12);

        int   nj = g_idx[cg * NS + lane];
        float gx = g_gx[cg * NS + lane];
        float gy = g_gy[cg * NS + lane];
        float gz = g_gz[cg * NS + lane];

        float h1[8];
#pragma unroll
        for (int o = 0; o < 8; o++)
            h1[o] = leaky(fmaf(sW[o*3+0], gx, fmaf(sW[o*3+1], gy, fmaf(sW[o*3+2], gz, sW[24+o]))));
        float h2[16];
#pragma unroll
        for (int o = 0; o < 16; o++) {
            float a = sW[160 + o];
#pragma unroll
            for (int i = 0; i < 8; i++) a = fmaf(sW[32 + o*8 + i], h1[i], a);
            h2[o] = leaky(a);
        }
        float wv[16], w2sum = 0.0f;
#pragma unroll
        for (int o = 0; o < 16; o++) {
            float a = sW[432 + o];
#pragma unroll
            for (int i = 0; i < 16; i++) a = fmaf(sW[176 + o*16 + i], h2[i], a);
            wv[o] = a; w2sum = fmaf(a, a, w2sum);
        }
        float inv1 = rsqrtf(fmaxf(w2sum, 1e-8f));

        float wn[16];
#pragma unroll
        for (int kk = 0; kk < 16; kk++) {
            float t = wv[kk] * wv[kk];
#pragma unroll
            for (int off = 16; off; off >>= 1) t += __shfl_xor_sync(0xffffffffu, t, off);
            float s2 = fmaxf(sqrtf(fmaxf(t, 1e-8f)), 1.0f);
            wn[kk] = wv[kk] * inv1 * (1.0f / s2);
        }

        float4* swf4 = (float4*)swf;
#pragma unroll
        for (int q = 0; q < 4; q++)
            swf4[q * 32 + lane] = make_float4(wn[4*q], wn[4*q+1], wn[4*q+2], wn[4*q+3]);
        snj[lane] = nj;
        __syncwarp();

        const float* fT = g_featT + (size_t)bb * NN * CC;
        float2 buf[8];
#pragma unroll
        for (int p = 0; p < 8; p++)
            buf[p] = *(const float2*)(fT + (size_t)snj[p] * CC + 2 * lane);

        float acc0[16], acc1[16];
#pragma unroll
        for (int kk = 0; kk < 16; kk++) { acc0[kk] = 0.0f; acc1[kk] = 0.0f; }

#pragma unroll
        for (int s = 0; s < 32; s++) {
            float2 f = buf[s & 7];
            if (s < 24)
                buf[s & 7] = *(const float2*)(fT + (size_t)snj[s + 8] * CC + 2 * lane);
            float4 q0 = swf4[s], q1 = swf4[32 + s], q2 = swf4[64 + s], q3 = swf4[96 + s];
            acc0[0]  = fmaf(q0.x, f.x, acc0[0]);  acc1[0]  = fmaf(q0.x, f.y, acc1[0]);
            acc0[1]  = fmaf(q0.y, f.x, acc0[1]);  acc1[1]  = fmaf(q0.y, f.y, acc1[1]);
            acc0[2]  = fmaf(q0.z, f.x, acc0[2]);  acc1[2]  = fmaf(q0.z, f.y, acc1[2]);
            acc0[3]  = fmaf(q0.w, f.x, acc0[3]);  acc1[3]  = fmaf(q0.w, f.y, acc1[3]);
            acc0[4]  = fmaf(q1.x, f.x, acc0[4]);  acc1[4]  = fmaf(q1.x, f.y, acc1[4]);
            acc0[5]  = fmaf(q1.y, f.x, acc0[5]);  acc1[5]  = fmaf(q1.y, f.y, acc1[5]);
            acc0[6]  = fmaf(q1.z, f.x, acc0[6]);  acc1[6]  = fmaf(q1.z, f.y, acc1[6]);
            acc0[7]  = fmaf(q1.w, f.x, acc0[7]);  acc1[7]  = fmaf(q1.w, f.y, acc1[7]);
            acc0[8]  = fmaf(q2.x, f.x, acc0[8]);  acc1[8]  = fmaf(q2.x, f.y, acc1[8]);
            acc0[9]  = fmaf(q2.y, f.x, acc0[9]);  acc1[9]  = fmaf(q2.y, f.y, acc1[9]);
            acc0[10] = fmaf(q2.z, f.x, acc0[10]); acc1[10] = fmaf(q2.z, f.y, acc1[10]);
            acc0[11] = fmaf(q2.w, f.x, acc0[11]); acc1[11] = fmaf(q2.w, f.y, acc1[11]);
            acc0[12] = fmaf(q3.x, f.x, acc0[12]); acc1[12] = fmaf(q3.x, f.y, acc1[12]);
            acc0[13] = fmaf(q3.y, f.x, acc0[13]); acc1[13] = fmaf(q3.y, f.y, acc1[13]);
            acc0[14] = fmaf(q3.z, f.x, acc0[14]); acc1[14] = fmaf(q3.z, f.y, acc1[14]);
            acc0[15] = fmaf(q3.w, f.x, acc0[15]); acc1[15] = fmaf(q3.w, f.y, acc1[15]);
        }

        float* orow = g_projL + cg * 1024;
#pragma unroll
        for (int kk = 0; kk < 16; kk++)
            *(float2*)(orow + kk * 64 + 2 * lane) =
                make_float2(leaky(acc0[kk]), leaky(acc1[kk]));
        __syncwarp();
    }
}

// ---------------- GEMM (tf32 tensor cores, 3xTF32 split) ----------------
// C[128 bn, 64 o] per block; K=1024 in 32-wide double-buffered stages.
// smem floats: A: 2 x 128*36, B: 2 x 64*36  (13824 floats = 55296 B)
// epilogue reuses smem as sO[64][140].
#define GEMM_SMEM_BYTES (13824 * 4)

__global__ __launch_bounds__(256) void gemm_tf32_kernel(
    const float* __restrict__ bc, float* __restrict__ out)
{
    extern __shared__ float sm[];
    float* sA0 = sm;            // 4608
    float* sA1 = sm + 4608;
    float* sB0 = sm + 9216;     // 2304
    float* sB1 = sm + 11520;

    int tid = threadIdx.x, lane = tid & 31, w = tid >> 5;
    size_t row0 = (size_t)blockIdx.x * 128;
    int b = (int)(row0 >> 12), n0 = (int)(row0 & 4095);
    const float* pA = g_projL + row0 * 1024;

    // global staging indices
    int ar = tid >> 1;              // 0..127
    int ak = (tid & 1) * 16;        // 0/16
    int br = tid >> 2;              // 0..63
    int bk = (tid & 3) * 8;         // 0..24

    int wi = (w & 3) * 32;          // i tile
    int wj = (w >> 2) * 32;         // j tile

    float acc[2][4][4];
#pragma unroll
    for (int i = 0; i < 2; i++)
#pragma unroll
        for (int j = 0; j < 4; j++)
#pragma unroll
            for (int q = 0; q < 4; q++) acc[i][j][q] = 0.0f;

    float4 aR[4], bR[2];
    {   // stage 0 loads
        const float4* s = (const float4*)(pA + (size_t)ar * 1024 + ak);
        aR[0] = s[0]; aR[1] = s[1]; aR[2] = s[2]; aR[3] = s[3];
        const float4* t = (const float4*)(g_WcP + (size_t)br * 1024 + bk);
        bR[0] = t[0]; bR[1] = t[1];
    }
    {   // stage 0 store
        float* p = sA0 + ar * 36 + ak;
#pragma unroll
        for (int q = 0; q < 4; q++) {
            p[4*q+0] = ((float*)&aR[q])[0]; p[4*q+1] = ((float*)&aR[q])[1];
            p[4*q+2] = ((float*)&aR[q])[2]; p[4*q+3] = ((float*)&aR[q])[3];
        }
        float* pb = sB0 + br * 36 + bk;
#pragma unroll
        for (int q = 0; q < 2; q++) {
            pb[4*q+0] = ((float*)&bR[q])[0]; pb[4*q+1] = ((float*)&bR[q])[1];
            pb[4*q+2] = ((float*)&bR[q])[2]; pb[4*q+3] = ((float*)&bR[q])[3];
        }
    }
    __syncthreads();

    for (int s = 0; s < 32; s++) {
        if (s + 1 < 32) {
            int k0 = (s + 1) * 32;
            const float4* sa = (const float4*)(pA + (size_t)ar * 1024 + k0 + ak);
            aR[0] = sa[0]; aR[1] = sa[1]; aR[2] = sa[2]; aR[3] = sa[3];
            const float4* tb = (const float4*)(g_WcP + (size_t)br * 1024 + k0 + bk);
            bR[0] = tb[0]; bR[1] = tb[1];
        }
        const float* A  = (s & 1) ? sA1 : sA0;
        const float* Bs = (s & 1) ? sB1 : sB0;

#pragma unroll
        for (int kk = 0; kk < 32; kk += 8) {
            uint32_t ah[2][4], al[2][4];
#pragma unroll
            for (int ii = 0; ii < 2; ii++) {
                int rb = (wi + ii * 16 + (lane >> 2)) * 36 + kk + (lane & 3);
                float x0 = A[rb];
                float x1 = A[rb + 8 * 36];
                float x2 = A[rb + 4];
                float x3 = A[rb + 8 * 36 + 4];
                tf32split(x0, ah[ii][0], al[ii][0]);
                tf32split(x1, ah[ii][1], al[ii][1]);
                tf32split(x2, ah[ii][2], al[ii][2]);
                tf32split(x3, ah[ii][3], al[ii][3]);
            }
            uint32_t bh[4][2], bl[4][2];
#pragma unroll
            for (int jj = 0; jj < 4; jj++) {
                int ob = (wj + jj * 8 + (lane >> 2)) * 36 + kk + (lane & 3);
                float y0 = Bs[ob];
                float y1 = Bs[ob + 4];
                tf32split(y0, bh[jj][0], bl[jj][0]);
                tf32split(y1, bh[jj][1], bl[jj][1]);
            }
#pragma unroll
            for (int ii = 0; ii < 2; ii++)
#pragma unroll
                for (int jj = 0; jj < 4; jj++) {
                    mma_tf32(acc[ii][jj], ah[ii], bh[jj]);
                    mma_tf32(acc[ii][jj], ah[ii], bl[jj]);
                    mma_tf32(acc[ii][jj], al[ii], bh[jj]);
                }
        }

        if (s + 1 < 32) {
            float* p = ((s + 1) & 1) ? sA1 : sA0;
            p += ar * 36 + ak;
#pragma unroll
            for (int q = 0; q < 4; q++) {
                p[4*q+0] = ((float*)&aR[q])[0]; p[4*q+1] = ((float*)&aR[q])[1];
                p[4*q+2] = ((float*)&aR[q])[2]; p[4*q+3] = ((float*)&aR[q])[3];
            }
            float* pb = (((s + 1) & 1) ? sB1 : sB0) + br * 36 + bk;
#pragma unroll
            for (int q = 0; q < 2; q++) {
                pb[4*q+0] = ((float*)&bR[q])[0]; pb[4*q+1] = ((float*)&bR[q])[1];
                pb[4*q+2] = ((float*)&bR[q])[2]; pb[4*q+3] = ((float*)&bR[q])[3];
            }
        }
        __syncthreads();
    }

    // ---- epilogue via smem (stride 140), fully coalesced out ----
    float* sO = sm;
#pragma unroll
    for (int ii = 0; ii < 2; ii++)
#pragma unroll
        for (int jj = 0; jj < 4; jj++) {
            int r = wi + ii * 16 + (lane >> 2);
            int o = wj + jj * 8 + (lane & 3) * 2;
            float b0v = __ldg(&bc[o]), b1v = __ldg(&bc[o + 1]);
            sO[o * 140 + r]           = leaky(acc[ii][jj][0] + b0v);
            sO[(o + 1) * 140 + r]     = leaky(acc[ii][jj][1] + b1v);
            sO[o * 140 + r + 8]       = leaky(acc[ii][jj][2] + b0v);
            sO[(o + 1) * 140 + r + 8] = leaky(acc[ii][jj][3] + b1v);
        }
    __syncthreads();

    int oo = tid >> 2, c4 = (tid & 3) * 4;
    float* orow = out + (size_t)b * (OUTC * NN) + (size_t)oo * NN + n0;
#pragma unroll
    for (int q = 0; q < 8; q++) {
        float4 v = *(float4*)&sO[oo * 140 + c4 + q * 16];
        *(float4*)&orow[c4 + q * 16] = v;
    }
}

extern "C" void kernel_launch(void* const* d_in, const int* in_sizes, int n_in,
                              void* d_out, int out_size) {
    const float* xyz  = (const float*)d_in[0];
    const float* feat = (const float*)d_in[1];
    const float* W1 = (const float*)d_in[2];
    const float* b1 = (const float*)d_in[3];
    const float* W2 = (const float*)d_in[4];
    const float* b2 = (const float*)d_in[5];
    const float* W3 = (const float*)d_in[6];
    const float* b3 = (const float*)d_in[7];
    const float* Wc = (const float*)d_in[8];
    const float* bc = (const float*)d_in[9];

    float* out = (float*)d_out;
    float* out_main = out;
    const int xyz_elems = BB * NN * 3;
    const int out_elems = BB * OUTC * NN;
    if (out_size == xyz_elems + out_elems) {
        cudaMemcpyAsync(out, xyz, (size_t)xyz_elems * sizeof(float), cudaMemcpyDeviceToDevice);
        out_main = out + xyz_elems;
    }

    transpose_kernel<<<dim3(NN / 32, CC / 32, BB), dim3(32, 8)>>>(feat);
    wcperm_kernel<<<(OUTC * 1024) / 256, 256>>>(Wc);

    cudaFuncSetAttribute(knn_kernel, cudaFuncAttributeMaxDynamicSharedMemorySize, (int)KNN_SMEM);
    knn_kernel<<<dim3(NN / 32, BB), 256, KNN_SMEM>>>(xyz);

    projgen_kernel<<<(BB * NN) / (8 * CW), 256>>>(W1, b1, W2, b2, W3, b3);

    cudaFuncSetAttribute(gemm_tf32_kernel, cudaFuncAttributeMaxDynamicSharedMemorySize, GEMM_SMEM_BYTES);
    gemm_tf32_kernel<<<(BB * NN) / 128, 256, GEMM_SMEM_BYTES>>>(bc, out_main);
}

// round 4
// speedup vs baseline: 2.3427x; 1.0459x over previous
#include <cuda_runtime.h>
#include <cuda_bf16.h>
#include <cstdint>

#define BB 8
#define NN 4096
#define CC 64
#define OUTC 64
#define NS 32
#define R2C 0.04f
#define ALPHA 0.2f
#define CAPK 224

// ---- device scratch (allocation-free rule) ----
__device__ float g_featT[(size_t)BB * NN * CC];                 // (B,N,C) 8 MB
__device__ __nv_bfloat16 g_projLb[(size_t)BB * NN * 2048];      // per row: hi[1024], lo[1024] (kc-major)
__device__ __nv_bfloat16 g_WcPb[(size_t)OUTC * 2048];           // per row: hi[1024], lo[1024]
__device__ int   g_idx[(size_t)BB * NN * NS];
__device__ float g_gx [(size_t)BB * NN * NS];
__device__ float g_gy [(size_t)BB * NN * NS];
__device__ float g_gz [(size_t)BB * NN * NS];

__device__ __forceinline__ float leaky(float x) { return fmaxf(x, ALPHA * x); }

__device__ __forceinline__ uint32_t pack_hi(float v0, float v1, float& r0, float& r1) {
    __nv_bfloat16 h0 = __float2bfloat16_rn(v0);
    __nv_bfloat16 h1 = __float2bfloat16_rn(v1);
    r0 = v0 - __bfloat162float(h0);
    r1 = v1 - __bfloat162float(h1);
    uint32_t w;
    uint16_t u0 = *(uint16_t*)&h0, u1 = *(uint16_t*)&h1;
    w = ((uint32_t)u1 << 16) | u0;
    return w;
}
__device__ __forceinline__ uint32_t pack_bf2(float v0, float v1) {
    __nv_bfloat16 h0 = __float2bfloat16_rn(v0);
    __nv_bfloat16 h1 = __float2bfloat16_rn(v1);
    uint16_t u0 = *(uint16_t*)&h0, u1 = *(uint16_t*)&h1;
    return ((uint32_t)u1 << 16) | u0;
}

__device__ __forceinline__ void mma_bf16(float* c, const uint32_t* a, const uint32_t* b) {
    asm volatile(
        "mma.sync.aligned.m16n8k16.row.col.f32.bf16.bf16.f32 "
        "{%0,%1,%2,%3}, {%4,%5,%6,%7}, {%8,%9}, {%0,%1,%2,%3};"
        : "+f"(c[0]), "+f"(c[1]), "+f"(c[2]), "+f"(c[3])
        : "r"(a[0]), "r"(a[1]), "r"(a[2]), "r"(a[3]), "r"(b[0]), "r"(b[1]));
}

// ---------------- transpose: (B,C,N) -> (B,N,C) ----------------
__global__ void transpose_kernel(const float* __restrict__ feat) {
    __shared__ float tile[32][33];
    int b = blockIdx.z, n0 = blockIdx.x * 32, c0 = blockIdx.y * 32;
    int tx = threadIdx.x, ty = threadIdx.y;
    const float* fb = feat + (size_t)b * CC * NN;
    float* ob = g_featT + (size_t)b * NN * CC;
#pragma unroll
    for (int i = 0; i < 4; i++)
        tile[ty + i * 8][tx] = fb[(size_t)(c0 + ty + i * 8) * NN + n0 + tx];
    __syncthreads();
#pragma unroll
    for (int i = 0; i < 4; i++)
        ob[(size_t)(n0 + ty + i * 8) * CC + c0 + tx] = tile[tx][ty + i * 8];
}

// ---------------- Wc permute + bf16 split: WcPb[o] rows of hi[kc],lo[kc], kc=k*64+c ----------------
__global__ void wcperm_kernel(const float* __restrict__ Wc) {
    int idx = blockIdx.x * 256 + threadIdx.x;   // 32768 pairs
    int o = idx >> 9, pair = idx & 511;
    int kc0 = pair * 2;
    int c = kc0 & 63, k = kc0 >> 6;             // c even, pair shares k
    float x0 = Wc[o * 1024 + c * 16 + k];
    float x1 = Wc[o * 1024 + (c + 1) * 16 + k];
    float r0, r1;
    uint32_t hw = pack_hi(x0, x1, r0, r1);
    uint32_t lw = pack_bf2(r0, r1);
    uint32_t* row = (uint32_t*)(g_WcPb + (size_t)o * 2048);
    row[pair] = hw;
    row[512 + pair] = lw;
}

// ---------------- KNN: radius scan + rank selection ----------------
#define KNN_SMEM (size_t)(3 * NN * 4 + 8 * 4 * CAPK * 8)

__global__ __launch_bounds__(256, 2) void knn_kernel(const float* __restrict__ xyz) {
    extern __shared__ char smem_raw[];
    float* sx = (float*)smem_raw;
    float* sy = sx + NN;
    float* sz = sy + NN;
    unsigned long long* candAll = (unsigned long long*)(sz + NN);

    int b = blockIdx.y, tid = threadIdx.x, w = tid >> 5, lane = tid & 31;
    const float* xb = xyz + (size_t)b * NN * 3;
    for (int i = tid; i < NN; i += 256) {
        sx[i] = xb[i * 3 + 0];
        sy[i] = xb[i * 3 + 1];
        sz[i] = xb[i * 3 + 2];
    }
    __syncthreads();

    int nbase = blockIdx.x * 32 + w * 4;
    unsigned long long* cand0 = candAll + (size_t)w * 4 * CAPK;
    float cx[4], cy[4], cz[4];
    int cnt[4];
#pragma unroll
    for (int i = 0; i < 4; i++) {
        cx[i] = sx[nbase + i]; cy[i] = sy[nbase + i]; cz[i] = sz[nbase + i];
        cnt[i] = 0;
    }
    unsigned lmask = (1u << lane) - 1u;

    for (int j = lane; j < NN; j += 32) {
        float px = sx[j], py = sy[j], pz = sz[j];
#pragma unroll
        for (int i = 0; i < 4; i++) {
            float dx = px - cx[i], dy = py - cy[i], dz = pz - cz[i];
            float d2 = fmaf(dx, dx, fmaf(dy, dy, dz * dz));
            bool in = (d2 <= R2C);
            unsigned m = __ballot_sync(0xffffffffu, in);
            if (in) {
                int pos = cnt[i] + __popc(m & lmask);
                if (pos < CAPK)
                    cand0[i * CAPK + pos] =
                        ((unsigned long long)__float_as_uint(d2) << 32) | (unsigned)j;
            }
            cnt[i] += __popc(m);
        }
    }
    __syncwarp();

#pragma unroll
    for (int i = 0; i < 4; i++) {
        int n = nbase + i;
        size_t cg = (size_t)b * NN + n;
        int M = min(cnt[i], CAPK);
        const unsigned long long* cd = cand0 + i * CAPK;

        if (lane >= M) {
            g_idx[cg * NS + lane] = n;
            g_gx[cg * NS + lane] = 0.0f;
            g_gy[cg * NS + lane] = 0.0f;
            g_gz[cg * NS + lane] = 0.0f;
        }
        unsigned long long k[7];
        int r[7];
#pragma unroll
        for (int t = 0; t < 7; t++) {
            int p = lane + 32 * t;
            k[t] = (p < M) ? cd[p] : ~0ull;
            r[t] = 0;
        }
        for (int q = 0; q < M; q++) {
            unsigned long long kq = cd[q];
#pragma unroll
            for (int t = 0; t < 7; t++) r[t] += (kq < k[t]);
        }
#pragma unroll
        for (int t = 0; t < 7; t++) {
            int p = lane + 32 * t;
            if (p < M && r[t] < NS) {
                int jj = (int)(k[t] & 0xffffffffull);
                g_idx[cg * NS + r[t]] = jj;
                g_gx[cg * NS + r[t]] = sx[jj] - cx[i];
                g_gy[cg * NS + r[t]] = sy[jj] - cy[i];
                g_gz[cg * NS + r[t]] = sz[jj] - cz[i];
            }
        }
        __syncwarp();
    }
}

// ---------------- projgen: MLP + normalize + rank-32 proj, bf16-split output ----------------
#define CW 2
__global__ __launch_bounds__(256) void projgen_kernel(
    const float* __restrict__ W1, const float* __restrict__ b1,
    const float* __restrict__ W2, const float* __restrict__ b2,
    const float* __restrict__ W3, const float* __restrict__ b3)
{
    __shared__ float swfAll[8][512];
    __shared__ int   snjAll[8][32];
    __shared__ float sW[448];

    int tid = threadIdx.x, w = tid >> 5, lane = tid & 31;
    if (tid < 24)  sW[tid] = W1[tid];
    if (tid < 8)   sW[24 + tid] = b1[tid];
    if (tid < 128) sW[32 + tid] = W2[tid];
    if (tid < 16)  sW[160 + tid] = b2[tid];
    sW[176 + tid] = W3[tid];
    if (tid < 16)  sW[432 + tid] = b3[tid];
    __syncthreads();

    float* swf = swfAll[w];
    int* snj = snjAll[w];

    for (int it = 0; it < CW; it++) {
        size_t cg = (size_t)blockIdx.x * (8 * CW) + w * CW + it;
        int bb = (int)(cg >> 12);

        int   nj = g_idx[cg * NS + lane];
        float gx = g_gx[cg * NS + lane];
        float gy = g_gy[cg * NS + lane];
        float gz = g_gz[cg * NS + lane];

        float h1[8];
#pragma unroll
        for (int o = 0; o < 8; o++)
            h1[o] = leaky(fmaf(sW[o*3+0], gx, fmaf(sW[o*3+1], gy, fmaf(sW[o*3+2], gz, sW[24+o]))));
        float h2[16];
#pragma unroll
        for (int o = 0; o < 16; o++) {
            float a = sW[160 + o];
#pragma unroll
            for (int i = 0; i < 8; i++) a = fmaf(sW[32 + o*8 + i], h1[i], a);
            h2[o] = leaky(a);
        }
        float wv[16], w2sum = 0.0f;
#pragma unroll
        for (int o = 0; o < 16; o++) {
            float a = sW[432 + o];
#pragma unroll
            for (int i = 0; i < 16; i++) a = fmaf(sW[176 + o*16 + i], h2[i], a);
            wv[o] = a; w2sum = fmaf(a, a, w2sum);
        }
        float inv1 = rsqrtf(fmaxf(w2sum, 1e-8f));

        float wn[16];
#pragma unroll
        for (int kk = 0; kk < 16; kk++) {
            float t = wv[kk] * wv[kk];
#pragma unroll
            for (int off = 16; off; off >>= 1) t += __shfl_xor_sync(0xffffffffu, t, off);
            float s2 = fmaxf(sqrtf(fmaxf(t, 1e-8f)), 1.0f);
            wn[kk] = wv[kk] * inv1 * (1.0f / s2);
        }

        float4* swf4 = (float4*)swf;
#pragma unroll
        for (int q = 0; q < 4; q++)
            swf4[q * 32 + lane] = make_float4(wn[4*q], wn[4*q+1], wn[4*q+2], wn[4*q+3]);
        snj[lane] = nj;
        __syncwarp();

        const float* fT = g_featT + (size_t)bb * NN * CC;
        float2 buf[8];
#pragma unroll
        for (int p = 0; p < 8; p++)
            buf[p] = *(const float2*)(fT + (size_t)snj[p] * CC + 2 * lane);

        float acc0[16], acc1[16];
#pragma unroll
        for (int kk = 0; kk < 16; kk++) { acc0[kk] = 0.0f; acc1[kk] = 0.0f; }

#pragma unroll
        for (int s = 0; s < 32; s++) {
            float2 f = buf[s & 7];
            if (s < 24)
                buf[s & 7] = *(const float2*)(fT + (size_t)snj[s + 8] * CC + 2 * lane);
            float4 q0 = swf4[s], q1 = swf4[32 + s], q2 = swf4[64 + s], q3 = swf4[96 + s];
            acc0[0]  = fmaf(q0.x, f.x, acc0[0]);  acc1[0]  = fmaf(q0.x, f.y, acc1[0]);
            acc0[1]  = fmaf(q0.y, f.x, acc0[1]);  acc1[1]  = fmaf(q0.y, f.y, acc1[1]);
            acc0[2]  = fmaf(q0.z, f.x, acc0[2]);  acc1[2]  = fmaf(q0.z, f.y, acc1[2]);
            acc0[3]  = fmaf(q0.w, f.x, acc0[3]);  acc1[3]  = fmaf(q0.w, f.y, acc1[3]);
            acc0[4]  = fmaf(q1.x, f.x, acc0[4]);  acc1[4]  = fmaf(q1.x, f.y, acc1[4]);
            acc0[5]  = fmaf(q1.y, f.x, acc0[5]);  acc1[5]  = fmaf(q1.y, f.y, acc1[5]);
            acc0[6]  = fmaf(q1.z, f.x, acc0[6]);  acc1[6]  = fmaf(q1.z, f.y, acc1[6]);
            acc0[7]  = fmaf(q1.w, f.x, acc0[7]);  acc1[7]  = fmaf(q1.w, f.y, acc1[7]);
            acc0[8]  = fmaf(q2.x, f.x, acc0[8]);  acc1[8]  = fmaf(q2.x, f.y, acc1[8]);
            acc0[9]  = fmaf(q2.y, f.x, acc0[9]);  acc1[9]  = fmaf(q2.y, f.y, acc1[9]);
            acc0[10] = fmaf(q2.z, f.x, acc0[10]); acc1[10] = fmaf(q2.z, f.y, acc1[10]);
            acc0[11] = fmaf(q2.w, f.x, acc0[11]); acc1[11] = fmaf(q2.w, f.y, acc1[11]);
            acc0[12] = fmaf(q3.x, f.x, acc0[12]); acc1[12] = fmaf(q3.x, f.y, acc1[12]);
            acc0[13] = fmaf(q3.y, f.x, acc0[13]); acc1[13] = fmaf(q3.y, f.y, acc1[13]);
            acc0[14] = fmaf(q3.z, f.x, acc0[14]); acc1[14] = fmaf(q3.z, f.y, acc1[14]);
            acc0[15] = fmaf(q3.w, f.x, acc0[15]); acc1[15] = fmaf(q3.w, f.y, acc1[15]);
        }

        // write bf16 split, kc-major: word idx kk*32+lane (hi), 512+ (lo)
        uint32_t* row = (uint32_t*)(g_projLb + cg * 2048);
#pragma unroll
        for (int kk = 0; kk < 16; kk++) {
            float v0 = leaky(acc0[kk]), v1 = leaky(acc1[kk]);
            float r0, r1;
            uint32_t hw = pack_hi(v0, v1, r0, r1);
            uint32_t lw = pack_bf2(r0, r1);
            row[kk * 32 + lane] = hw;
            row[512 + kk * 32 + lane] = lw;
        }
        __syncwarp();
    }
}

// ---------------- GEMM (bf16 hi/lo split, m16n8k16) ----------------
// C[128 bn, 64 o] per block; K=1024 in 32-elem stages, double-buffered.
// smem words: A 2 planes x 128 rows x 20 + B 2 x 64 x 20, x2 buffers = 15360 words
#define AW (128 * 20)
#define BW (64 * 20)
#define STGW (2 * AW + 2 * BW)          // one buffer: 6.. (2 planes A + 2 planes B)
#define GEMM_SMEM_BYTES (2 * STGW * 4)  // 61440 B

__global__ __launch_bounds__(256) void gemm_bf16_kernel(
    const float* __restrict__ bc, float* __restrict__ out)
{
    extern __shared__ uint32_t smw[];
    // buffer layout per stage buffer: [Ah AW][Al AW][Bh BW][Bl BW]
    int tid = threadIdx.x, lane = tid & 31, w = tid >> 5;
    size_t row0 = (size_t)blockIdx.x * 128;
    int b = (int)(row0 >> 12), n0 = (int)(row0 & 4095);

    int ar = tid >> 1, ahalf = tid & 1;       // A: row 0..127, half 0/1 (words 0-7 / 8-15)
    int br = tid >> 2, bq = tid & 3;          // B: row 0..63, quarter (4 words each)

    const uint32_t* rowA = (const uint32_t*)(g_projLb + (row0 + ar) * 2048);
    const uint32_t* rowB = (const uint32_t*)(g_WcPb + (size_t)br * 2048);

    int wi = (w & 3) * 32;
    int wj = (w >> 2) * 32;

    float acc[2][4][4];
#pragma unroll
    for (int i = 0; i < 2; i++)
#pragma unroll
        for (int j = 0; j < 4; j++)
#pragma unroll
            for (int q = 0; q < 4; q++) acc[i][j][q] = 0.0f;

    uint4 aH0, aH1, aL0, aL1, bH, bL;
    // stage 0 global loads
    {
        const uint4* pAh = (const uint4*)(rowA + ahalf * 8);
        const uint4* pAl = (const uint4*)(rowA + 512 + ahalf * 8);
        aH0 = pAh[0]; aH1 = pAh[1]; aL0 = pAl[0]; aL1 = pAl[1];
        bH = *(const uint4*)(rowB + bq * 4);
        bL = *(const uint4*)(rowB + 512 + bq * 4);
    }
    // stage 0 smem store
    {
        uint32_t* buf = smw;
        *(uint4*)(buf + ar * 20 + ahalf * 8)          = aH0;
        *(uint4*)(buf + ar * 20 + ahalf * 8 + 4)      = aH1;
        *(uint4*)(buf + AW + ar * 20 + ahalf * 8)     = aL0;
        *(uint4*)(buf + AW + ar * 20 + ahalf * 8 + 4) = aL1;
        *(uint4*)(buf + 2 * AW + br * 20 + bq * 4)          = bH;
        *(uint4*)(buf + 2 * AW + BW + br * 20 + bq * 4)     = bL;
    }
    __syncthreads();

    for (int s = 0; s < 32; s++) {
        if (s + 1 < 32) {
            int wb = (s + 1) * 16;
            const uint4* pAh = (const uint4*)(rowA + wb + ahalf * 8);
            const uint4* pAl = (const uint4*)(rowA + 512 + wb + ahalf * 8);
            aH0 = pAh[0]; aH1 = pAh[1]; aL0 = pAl[0]; aL1 = pAl[1];
            bH = *(const uint4*)(rowB + wb + bq * 4);
            bL = *(const uint4*)(rowB + 512 + wb + bq * 4);
        }
        const uint32_t* buf = smw + (s & 1) * STGW;
        const uint32_t* Ah = buf;
        const uint32_t* Al = buf + AW;
        const uint32_t* Bh = buf + 2 * AW;
        const uint32_t* Bl = buf + 2 * AW + BW;

#pragma unroll
        for (int t = 0; t < 2; t++) {       // two k16 per stage
            int wb = t * 8;
            uint32_t ah[2][4], al[2][4];
#pragma unroll
            for (int ii = 0; ii < 2; ii++) {
                int r = wi + ii * 16 + (lane >> 2);
                int c0 = wb + (lane & 3);
                ah[ii][0] = Ah[r * 20 + c0];
                ah[ii][1] = Ah[(r + 8) * 20 + c0];
                ah[ii][2] = Ah[r * 20 + c0 + 4];
                ah[ii][3] = Ah[(r + 8) * 20 + c0 + 4];
                al[ii][0] = Al[r * 20 + c0];
                al[ii][1] = Al[(r + 8) * 20 + c0];
                al[ii][2] = Al[r * 20 + c0 + 4];
                al[ii][3] = Al[(r + 8) * 20 + c0 + 4];
            }
            uint32_t bh[4][2], bl[4][2];
#pragma unroll
            for (int jj = 0; jj < 4; jj++) {
                int n = wj + jj * 8 + (lane >> 2);
                int c0 = wb + (lane & 3);
                bh[jj][0] = Bh[n * 20 + c0];
                bh[jj][1] = Bh[n * 20 + c0 + 4];
                bl[jj][0] = Bl[n * 20 + c0];
                bl[jj][1] = Bl[n * 20 + c0 + 4];
            }
#pragma unroll
            for (int ii = 0; ii < 2; ii++)
#pragma unroll
                for (int jj = 0; jj < 4; jj++) {
                    mma_bf16(acc[ii][jj], ah[ii], bh[jj]);
                    mma_bf16(acc[ii][jj], ah[ii], bl[jj]);
                    mma_bf16(acc[ii][jj], al[ii], bh[jj]);
                }
        }

        if (s + 1 < 32) {
            uint32_t* nb = smw + ((s + 1) & 1) * STGW;
            *(uint4*)(nb + ar * 20 + ahalf * 8)          = aH0;
            *(uint4*)(nb + ar * 20 + ahalf * 8 + 4)      = aH1;
            *(uint4*)(nb + AW + ar * 20 + ahalf * 8)     = aL0;
            *(uint4*)(nb + AW + ar * 20 + ahalf * 8 + 4) = aL1;
            *(uint4*)(nb + 2 * AW + br * 20 + bq * 4)      = bH;
            *(uint4*)(nb + 2 * AW + BW + br * 20 + bq * 4) = bL;
        }
        __syncthreads();
    }

    // ---- epilogue via smem (stride 140 floats), coalesced out ----
    float* sO = (float*)smw;
#pragma unroll
    for (int ii = 0; ii < 2; ii++)
#pragma unroll
        for (int jj = 0; jj < 4; jj++) {
            int r = wi + ii * 16 + (lane >> 2);
            int o = wj + jj * 8 + (lane & 3) * 2;
            float b0v = __ldg(&bc[o]), b1v = __ldg(&bc[o + 1]);
            sO[o * 140 + r]           = leaky(acc[ii][jj][0] + b0v);
            sO[(o + 1) * 140 + r]     = leaky(acc[ii][jj][1] + b1v);
            sO[o * 140 + r + 8]       = leaky(acc[ii][jj][2] + b0v);
            sO[(o + 1) * 140 + r + 8] = leaky(acc[ii][jj][3] + b1v);
        }
    __syncthreads();

    int oo = tid >> 2, c4 = (tid & 3) * 4;
    float* orow = out + (size_t)b * (OUTC * NN) + (size_t)oo * NN + n0;
#pragma unroll
    for (int q = 0; q < 8; q++) {
        float4 v = *(float4*)&sO[oo * 140 + c4 + q * 16];
        *(float4*)&orow[c4 + q * 16] = v;
    }
}

extern "C" void kernel_launch(void* const* d_in, const int* in_sizes, int n_in,
                              void* d_out, int out_size) {
    const float* xyz  = (const float*)d_in[0];
    const float* feat = (const float*)d_in[1];
    const float* W1 = (const float*)d_in[2];
    const float* b1 = (const float*)d_in[3];
    const float* W2 = (const float*)d_in[4];
    const float* b2 = (const float*)d_in[5];
    const float* W3 = (const float*)d_in[6];
    const float* b3 = (const float*)d_in[7];
    const float* Wc = (const float*)d_in[8];
    const float* bc = (const float*)d_in[9];

    float* out = (float*)d_out;
    float* out_main = out;
    const int xyz_elems = BB * NN * 3;
    const int out_elems = BB * OUTC * NN;
    if (out_size == xyz_elems + out_elems) {
        cudaMemcpyAsync(out, xyz, (size_t)xyz_elems * sizeof(float), cudaMemcpyDeviceToDevice);
        out_main = out + xyz_elems;
    }

    transpose_kernel<<<dim3(NN / 32, CC / 32, BB), dim3(32, 8)>>>(feat);
    wcperm_kernel<<<(OUTC * 512) / 256, 256>>>(Wc);

    cudaFuncSetAttribute(knn_kernel, cudaFuncAttributeMaxDynamicSharedMemorySize, (int)KNN_SMEM);
    knn_kernel<<<dim3(NN / 32, BB), 256, KNN_SMEM>>>(xyz);

    projgen_kernel<<<(BB * NN) / (8 * CW), 256>>>(W1, b1, W2, b2, W3, b3);

    cudaFuncSetAttribute(gemm_bf16_kernel, cudaFuncAttributeMaxDynamicSharedMemorySize, GEMM_SMEM_BYTES);
    gemm_bf16_kernel<<<(BB * NN) / 128, 256, GEMM_SMEM_BYTES>>>(bc, out_main);
}

// round 6
// speedup vs baseline: 2.6782x; 1.1432x over previous
#include <cuda_runtime.h>
#include <cuda_bf16.h>
#include <cstdint>

#define BB 8
#define NN 4096
#define CC 64
#define OUTC 64
#define NS 32
#define R2C 0.04f
#define ALPHA 0.2f
#define CAPK 224
// full float bits of 0.0225f (= 0.15^2), exact tight threshold on the d2 word
#define TIGHT32 0x3CB850EBu
#define TIGHTKEY64 ((unsigned long long)TIGHT32 << 32)

// ---- device scratch (allocation-free rule) ----
__device__ float g_featT[(size_t)BB * NN * CC];                 // (B,N,C) 8 MB
__device__ __nv_bfloat16 g_projLb[(size_t)BB * NN * 2048];      // per row: hi[1024], lo[1024] (kc-major)
__device__ __nv_bfloat16 g_WcPb[(size_t)OUTC * 2048];           // per row: hi[1024], lo[1024]
__device__ int   g_idx[(size_t)BB * NN * NS];
__device__ float g_gx [(size_t)BB * NN * NS];
__device__ float g_gy [(size_t)BB * NN * NS];
__device__ float g_gz [(size_t)BB * NN * NS];

__device__ __forceinline__ float leaky(float x) { return fmaxf(x, ALPHA * x); }

__device__ __forceinline__ uint32_t pack_hi(float v0, float v1, float& r0, float& r1) {
    __nv_bfloat16 h0 = __float2bfloat16_rn(v0);
    __nv_bfloat16 h1 = __float2bfloat16_rn(v1);
    r0 = v0 - __bfloat162float(h0);
    r1 = v1 - __bfloat162float(h1);
    uint16_t u0 = *(uint16_t*)&h0, u1 = *(uint16_t*)&h1;
    return ((uint32_t)u1 << 16) | u0;
}
__device__ __forceinline__ uint32_t pack_bf2(float v0, float v1) {
    __nv_bfloat16 h0 = __float2bfloat16_rn(v0);
    __nv_bfloat16 h1 = __float2bfloat16_rn(v1);
    uint16_t u0 = *(uint16_t*)&h0, u1 = *(uint16_t*)&h1;
    return ((uint32_t)u1 << 16) | u0;
}

__device__ __forceinline__ void mma_bf16(float* c, const uint32_t* a, const uint32_t* b) {
    asm volatile(
        "mma.sync.aligned.m16n8k16.row.col.f32.bf16.bf16.f32 "
        "{%0,%1,%2,%3}, {%4,%5,%6,%7}, {%8,%9}, {%0,%1,%2,%3};"
        : "+f"(c[0]), "+f"(c[1]), "+f"(c[2]), "+f"(c[3])
        : "r"(a[0]), "r"(a[1]), "r"(a[2]), "r"(a[3]), "r"(b[0]), "r"(b[1]));
}

// ---------------- transpose: (B,C,N) -> (B,N,C) ----------------
__global__ void transpose_kernel(const float* __restrict__ feat) {
    __shared__ float tile[32][33];
    int b = blockIdx.z, n0 = blockIdx.x * 32, c0 = blockIdx.y * 32;
    int tx = threadIdx.x, ty = threadIdx.y;
    const float* fb = feat + (size_t)b * CC * NN;
    float* ob = g_featT + (size_t)b * NN * CC;
#pragma unroll
    for (int i = 0; i < 4; i++)
        tile[ty + i * 8][tx] = fb[(size_t)(c0 + ty + i * 8) * NN + n0 + tx];
    __syncthreads();
#pragma unroll
    for (int i = 0; i < 4; i++)
        ob[(size_t)(n0 + ty + i * 8) * CC + c0 + tx] = tile[tx][ty + i * 8];
}

// ---------------- Wc permute + bf16 split ----------------
__global__ void wcperm_kernel(const float* __restrict__ Wc) {
    int idx = blockIdx.x * 256 + threadIdx.x;   // 32768 pairs
    int o = idx >> 9, pair = idx & 511;
    int kc0 = pair * 2;
    int c = kc0 & 63, k = kc0 >> 6;
    float x0 = Wc[o * 1024 + c * 16 + k];
    float x1 = Wc[o * 1024 + (c + 1) * 16 + k];
    float r0, r1;
    uint32_t hw = pack_hi(x0, x1, r0, r1);
    uint32_t lw = pack_bf2(r0, r1);
    uint32_t* row = (uint32_t*)(g_WcPb + (size_t)o * 2048);
    row[pair] = hw;
    row[512 + pair] = lw;
}

// ---------------- KNN: radius scan + tight-filtered rank selection (u64 exact keys) ----------------
// smem: sx,sy,sz[4096] (48KB) + cand u64 [8 warps][4 centers][CAPK] (56KB)
#define KNN_SMEM (size_t)(3 * NN * 4 + 8 * 4 * CAPK * 8)

// rank loop versioned on list length; rr[t] += (cd[q] < kk[t]); u64 exact compares
#define RANK_LOOP(cd, Mlen, kk, rr)                                         \
    do {                                                                    \
        if ((Mlen) <= 64) {                                                 \
            for (int q = 0; q < (Mlen); q++) {                              \
                unsigned long long kq = (cd)[q];                            \
                rr[0] += (kq < kk[0]); rr[1] += (kq < kk[1]);               \
            }                                                               \
        } else if ((Mlen) <= 128) {                                         \
            for (int q = 0; q < (Mlen); q++) {                              \
                unsigned long long kq = (cd)[q];                            \
                rr[0] += (kq < kk[0]); rr[1] += (kq < kk[1]);               \
                rr[2] += (kq < kk[2]); rr[3] += (kq < kk[3]);               \
            }                                                               \
        } else {                                                            \
            for (int q = 0; q < (Mlen); q++) {                              \
                unsigned long long kq = (cd)[q];                            \
                rr[0] += (kq < kk[0]); rr[1] += (kq < kk[1]);               \
                rr[2] += (kq < kk[2]); rr[3] += (kq < kk[3]);               \
                rr[4] += (kq < kk[4]); rr[5] += (kq < kk[5]);               \
                rr[6] += (kq < kk[6]);                                      \
            }                                                               \
        }                                                                   \
    } while (0)

__global__ __launch_bounds__(256, 2) void knn_kernel(const float* __restrict__ xyz) {
    extern __shared__ char smem_raw[];
    float* sx = (float*)smem_raw;
    float* sy = sx + NN;
    float* sz = sy + NN;
    unsigned long long* candAll = (unsigned long long*)(sz + NN);

    int b = blockIdx.y, tid = threadIdx.x, w = tid >> 5, lane = tid & 31;
    const float* xb = xyz + (size_t)b * NN * 3;
    for (int i = tid; i < NN; i += 256) {
        sx[i] = xb[i * 3 + 0];
        sy[i] = xb[i * 3 + 1];
        sz[i] = xb[i * 3 + 2];
    }
    __syncthreads();

    int nbase = blockIdx.x * 32 + w * 4;
    unsigned long long* cand0 = candAll + (size_t)w * 4 * CAPK;
    float cx[4], cy[4], cz[4];
    int cnt[4];
#pragma unroll
    for (int i = 0; i < 4; i++) {
        cx[i] = sx[nbase + i]; cy[i] = sy[nbase + i]; cz[i] = sz[nbase + i];
        cnt[i] = 0;
    }
    unsigned lmask = (1u << lane) - 1u;

    for (int j = lane; j < NN; j += 32) {
        float px = sx[j], py = sy[j], pz = sz[j];
#pragma unroll
        for (int i = 0; i < 4; i++) {
            float dx = px - cx[i], dy = py - cy[i], dz = pz - cz[i];
            float d2 = fmaf(dx, dx, fmaf(dy, dy, dz * dz));
            bool in = (d2 <= R2C);
            unsigned m = __ballot_sync(0xffffffffu, in);
            if (in) {
                int pos = cnt[i] + __popc(m & lmask);
                if (pos < CAPK)
                    cand0[i * CAPK + pos] =
                        ((unsigned long long)__float_as_uint(d2) << 32) | (unsigned)j;
            }
            cnt[i] += __popc(m);
        }
    }
    __syncwarp();

#pragma unroll
    for (int i = 0; i < 4; i++) {
        int n = nbase + i;
        size_t cg = (size_t)b * NN + n;
        int M = min(cnt[i], CAPK);
        unsigned long long* cd = cand0 + i * CAPK;

        // slots >= M get self (gxyz = 0); only happens when M < 32
        if (lane >= M) {
            g_idx[cg * NS + lane] = n;
            g_gx[cg * NS + lane] = 0.0f;
            g_gy[cg * NS + lane] = 0.0f;
            g_gz[cg * NS + lane] = 0.0f;
        }

        // load my candidates into regs
        unsigned long long k[7];
#pragma unroll
        for (int t = 0; t < 7; t++) {
            int p = lane + 32 * t;
            k[t] = (p < M) ? cd[p] : ~0ull;
        }
        // count tight candidates (d2 < 0.15^2, exact high-word compare)
        unsigned bms[7];
        int Mt = 0;
#pragma unroll
        for (int t = 0; t < 7; t++) {
            bms[t] = __ballot_sync(0xffffffffu, k[t] < TIGHTKEY64);
            Mt += __popc(bms[t]);
        }

        if (Mt >= NS) {
            // compact tight keys to front; 32 nearest guaranteed inside
            int base = 0;
#pragma unroll
            for (int t = 0; t < 7; t++) {
                if (k[t] < TIGHTKEY64)
                    cd[base + __popc(bms[t] & lmask)] = k[t];
                base += __popc(bms[t]);
            }
            __syncwarp();
            unsigned long long k2[7];
            int rr[7];
#pragma unroll
            for (int t = 0; t < 7; t++) {
                int p = lane + 32 * t;
                k2[t] = (p < Mt) ? cd[p] : ~0ull;
                rr[t] = 0;
            }
            RANK_LOOP(cd, Mt, k2, rr);
#pragma unroll
            for (int t = 0; t < 7; t++) {
                int p = lane + 32 * t;
                if (p < Mt && rr[t] < NS) {
                    int jj = (int)(k2[t] & 0xffffffffull);
                    g_idx[cg * NS + rr[t]] = jj;
                    g_gx[cg * NS + rr[t]] = sx[jj] - cx[i];
                    g_gy[cg * NS + rr[t]] = sy[jj] - cy[i];
                    g_gz[cg * NS + rr[t]] = sz[jj] - cz[i];
                }
            }
        } else {
            // boundary centers: rank over the full list
            int rr[7];
#pragma unroll
            for (int t = 0; t < 7; t++) rr[t] = 0;
            RANK_LOOP(cd, M, k, rr);
#pragma unroll
            for (int t = 0; t < 7; t++) {
                int p = lane + 32 * t;
                if (p < M && rr[t] < NS) {
                    int jj = (int)(k[t] & 0xffffffffull);
                    g_idx[cg * NS + rr[t]] = jj;
                    g_gx[cg * NS + rr[t]] = sx[jj] - cx[i];
                    g_gy[cg * NS + rr[t]] = sy[jj] - cy[i];
                    g_gz[cg * NS + rr[t]] = sz[jj] - cz[i];
                }
            }
        }
        __syncwarp();
    }
}

// ---------------- projgen: MLP + normalize + rank-32 proj, bf16-split output ----------------
#define CW 2
__global__ __launch_bounds__(256) void projgen_kernel(
    const float* __restrict__ W1, const float* __restrict__ b1,
    const float* __restrict__ W2, const float* __restrict__ b2,
    const float* __restrict__ W3, const float* __restrict__ b3)
{
    __shared__ float swfAll[8][512];
    __shared__ int   snjAll[8][32];
    __shared__ float sW[448];

    int tid = threadIdx.x, w = tid >> 5, lane = tid & 31;
    if (tid < 24)  sW[tid] = W1[tid];
    if (tid < 8)   sW[24 + tid] = b1[tid];
    if (tid < 128) sW[32 + tid] = W2[tid];
    if (tid < 16)  sW[160 + tid] = b2[tid];
    sW[176 + tid] = W3[tid];
    if (tid < 16)  sW[432 + tid] = b3[tid];
    __syncthreads();

    float* swf = swfAll[w];
    int* snj = snjAll[w];

    for (int it = 0; it < CW; it++) {
        size_t cg = (size_t)blockIdx.x * (8 * CW) + w * CW + it;
        int bb = (int)(cg >> 12);

        int   nj = g_idx[cg * NS + lane];
        float gx = g_gx[cg * NS + lane];
        float gy = g_gy[cg * NS + lane];
        float gz = g_gz[cg * NS + lane];

        float h1[8];
#pragma unroll
        for (int o = 0; o < 8; o++)
            h1[o] = leaky(fmaf(sW[o*3+0], gx, fmaf(sW[o*3+1], gy, fmaf(sW[o*3+2], gz, sW[24+o]))));
        float h2[16];
#pragma unroll
        for (int o = 0; o < 16; o++) {
            float a = sW[160 + o];
#pragma unroll
            for (int i = 0; i < 8; i++) a = fmaf(sW[32 + o*8 + i], h1[i], a);
            h2[o] = leaky(a);
        }
        float wv[16], w2sum = 0.0f;
#pragma unroll
        for (int o = 0; o < 16; o++) {
            float a = sW[432 + o];
#pragma unroll
            for (int i = 0; i < 16; i++) a = fmaf(sW[176 + o*16 + i], h2[i], a);
            wv[o] = a; w2sum = fmaf(a, a, w2sum);
        }
        float inv1 = rsqrtf(fmaxf(w2sum, 1e-8f));

        float wn[16];
#pragma unroll
        for (int kk = 0; kk < 16; kk++) {
            float t = wv[kk] * wv[kk];
#pragma unroll
            for (int off = 16; off; off >>= 1) t += __shfl_xor_sync(0xffffffffu, t, off);
            float s2 = fmaxf(sqrtf(fmaxf(t, 1e-8f)), 1.0f);
            wn[kk] = wv[kk] * inv1 * (1.0f / s2);
        }

        float4* swf4 = (float4*)swf;
#pragma unroll
        for (int q = 0; q < 4; q++)
            swf4[q * 32 + lane] = make_float4(wn[4*q], wn[4*q+1], wn[4*q+2], wn[4*q+3]);
        snj[lane] = nj;
        __syncwarp();

        const float* fT = g_featT + (size_t)bb * NN * CC;
        float2 buf[8];
#pragma unroll
        for (int p = 0; p < 8; p++)
            buf[p] = *(const float2*)(fT + (size_t)snj[p] * CC + 2 * lane);

        float acc0[16], acc1[16];
#pragma unroll
        for (int kk = 0; kk < 16; kk++) { acc0[kk] = 0.0f; acc1[kk] = 0.0f; }

#pragma unroll
        for (int s = 0; s < 32; s++) {
            float2 f = buf[s & 7];
            if (s < 24)
                buf[s & 7] = *(const float2*)(fT + (size_t)snj[s + 8] * CC + 2 * lane);
            float4 q0 = swf4[s], q1 = swf4[32 + s], q2 = swf4[64 + s], q3 = swf4[96 + s];
            acc0[0]  = fmaf(q0.x, f.x, acc0[0]);  acc1[0]  = fmaf(q0.x, f.y, acc1[0]);
            acc0[1]  = fmaf(q0.y, f.x, acc0[1]);  acc1[1]  = fmaf(q0.y, f.y, acc1[1]);
            acc0[2]  = fmaf(q0.z, f.x, acc0[2]);  acc1[2]  = fmaf(q0.z, f.y, acc1[2]);
            acc0[3]  = fmaf(q0.w, f.x, acc0[3]);  acc1[3]  = fmaf(q0.w, f.y, acc1[3]);
            acc0[4]  = fmaf(q1.x, f.x, acc0[4]);  acc1[4]  = fmaf(q1.x, f.y, acc1[4]);
            acc0[5]  = fmaf(q1.y, f.x, acc0[5]);  acc1[5]  = fmaf(q1.y, f.y, acc1[5]);
            acc0[6]  = fmaf(q1.z, f.x, acc0[6]);  acc1[6]  = fmaf(q1.z, f.y, acc1[6]);
            acc0[7]  = fmaf(q1.w, f.x, acc0[7]);  acc1[7]  = fmaf(q1.w, f.y, acc1[7]);
            acc0[8]  = fmaf(q2.x, f.x, acc0[8]);  acc1[8]  = fmaf(q2.x, f.y, acc1[8]);
            acc0[9]  = fmaf(q2.y, f.x, acc0[9]);  acc1[9]  = fmaf(q2.y, f.y, acc1[9]);
            acc0[10] = fmaf(q2.z, f.x, acc0[10]); acc1[10] = fmaf(q2.z, f.y, acc1[10]);
            acc0[11] = fmaf(q2.w, f.x, acc0[11]); acc1[11] = fmaf(q2.w, f.y, acc1[11]);
            acc0[12] = fmaf(q3.x, f.x, acc0[12]); acc1[12] = fmaf(q3.x, f.y, acc1[12]);
            acc0[13] = fmaf(q3.y, f.x, acc0[13]); acc1[13] = fmaf(q3.y, f.y, acc1[13]);
            acc0[14] = fmaf(q3.z, f.x, acc0[14]); acc1[14] = fmaf(q3.z, f.y, acc1[14]);
            acc0[15] = fmaf(q3.w, f.x, acc0[15]); acc1[15] = fmaf(q3.w, f.y, acc1[15]);
        }

        uint32_t* row = (uint32_t*)(g_projLb + cg * 2048);
#pragma unroll
        for (int kk = 0; kk < 16; kk++) {
            float v0 = leaky(acc0[kk]), v1 = leaky(acc1[kk]);
            float r0, r1;
            uint32_t hw = pack_hi(v0, v1, r0, r1);
            uint32_t lw = pack_bf2(r0, r1);
            row[kk * 32 + lane] = hw;
            row[512 + kk * 32 + lane] = lw;
        }
        __syncwarp();
    }
}

// ---------------- GEMM (bf16 hi/lo split, m16n8k16) ----------------
#define AW (128 * 20)
#define BW (64 * 20)
#define STGW (2 * AW + 2 * BW)
#define GEMM_SMEM_BYTES (2 * STGW * 4)

__global__ __launch_bounds__(256) void gemm_bf16_kernel(
    const float* __restrict__ bc, float* __restrict__ out)
{
    extern __shared__ uint32_t smw[];
    int tid = threadIdx.x, lane = tid & 31, w = tid >> 5;
    size_t row0 = (size_t)blockIdx.x * 128;
    int b = (int)(row0 >> 12), n0 = (int)(row0 & 4095);

    int ar = tid >> 1, ahalf = tid & 1;
    int br = tid >> 2, bq = tid & 3;

    const uint32_t* rowA = (const uint32_t*)(g_projLb + (row0 + ar) * 2048);
    const uint32_t* rowB = (const uint32_t*)(g_WcPb + (size_t)br * 2048);

    int wi = (w & 3) * 32;
    int wj = (w >> 2) * 32;

    float acc[2][4][4];
#pragma unroll
    for (int i = 0; i < 2; i++)
#pragma unroll
        for (int j = 0; j < 4; j++)
#pragma unroll
            for (int q = 0; q < 4; q++) acc[i][j][q] = 0.0f;

    uint4 aH0, aH1, aL0, aL1, bH, bL;
    {
        const uint4* pAh = (const uint4*)(rowA + ahalf * 8);
        const uint4* pAl = (const uint4*)(rowA + 512 + ahalf * 8);
        aH0 = pAh[0]; aH1 = pAh[1]; aL0 = pAl[0]; aL1 = pAl[1];
        bH = *(const uint4*)(rowB + bq * 4);
        bL = *(const uint4*)(rowB + 512 + bq * 4);
    }
    {
        uint32_t* buf = smw;
        *(uint4*)(buf + ar * 20 + ahalf * 8)          = aH0;
        *(uint4*)(buf + ar * 20 + ahalf * 8 + 4)      = aH1;
        *(uint4*)(buf + AW + ar * 20 + ahalf * 8)     = aL0;
        *(uint4*)(buf + AW + ar * 20 + ahalf * 8 + 4) = aL1;
        *(uint4*)(buf + 2 * AW + br * 20 + bq * 4)          = bH;
        *(uint4*)(buf + 2 * AW + BW + br * 20 + bq * 4)     = bL;
    }
    __syncthreads();

    for (int s = 0; s < 32; s++) {
        if (s + 1 < 32) {
            int wb = (s + 1) * 16;
            const uint4* pAh = (const uint4*)(rowA + wb + ahalf * 8);
            const uint4* pAl = (const uint4*)(rowA + 512 + wb + ahalf * 8);
            aH0 = pAh[0]; aH1 = pAh[1]; aL0 = pAl[0]; aL1 = pAl[1];
            bH = *(const uint4*)(rowB + wb + bq * 4);
            bL = *(const uint4*)(rowB + 512 + wb + bq * 4);
        }
        const uint32_t* buf = smw + (s & 1) * STGW;
        const uint32_t* Ah = buf;
        const uint32_t* Al = buf + AW;
        const uint32_t* Bh = buf + 2 * AW;
        const uint32_t* Bl = buf + 2 * AW + BW;

#pragma unroll
        for (int t = 0; t < 2; t++) {
            int wb = t * 8;
            uint32_t ah[2][4], al[2][4];
#pragma unroll
            for (int ii = 0; ii < 2; ii++) {
                int r = wi + ii * 16 + (lane >> 2);
                int c0 = wb + (lane & 3);
                ah[ii][0] = Ah[r * 20 + c0];
                ah[ii][1] = Ah[(r + 8) * 20 + c0];
                ah[ii][2] = Ah[r * 20 + c0 + 4];
                ah[ii][3] = Ah[(r + 8) * 20 + c0 + 4];
                al[ii][0] = Al[r * 20 + c0];
                al[ii][1] = Al[(r + 8) * 20 + c0];
                al[ii][2] = Al[r * 20 + c0 + 4];
                al[ii][3] = Al[(r + 8) * 20 + c0 + 4];
            }
            uint32_t bh[4][2], bl[4][2];
#pragma unroll
            for (int jj = 0; jj < 4; jj++) {
                int n = wj + jj * 8 + (lane >> 2);
                int c0 = wb + (lane & 3);
                bh[jj][0] = Bh[n * 20 + c0];
                bh[jj][1] = Bh[n * 20 + c0 + 4];
                bl[jj][0] = Bl[n * 20 + c0];
                bl[jj][1] = Bl[n * 20 + c0 + 4];
            }
#pragma unroll
            for (int ii = 0; ii < 2; ii++)
#pragma unroll
                for (int jj = 0; jj < 4; jj++) {
                    mma_bf16(acc[ii][jj], ah[ii], bh[jj]);
                    mma_bf16(acc[ii][jj], ah[ii], bl[jj]);
                    mma_bf16(acc[ii][jj], al[ii], bh[jj]);
                }
        }

        if (s + 1 < 32) {
            uint32_t* nb = smw + ((s + 1) & 1) * STGW;
            *(uint4*)(nb + ar * 20 + ahalf * 8)          = aH0;
            *(uint4*)(nb + ar * 20 + ahalf * 8 + 4)      = aH1;
            *(uint4*)(nb + AW + ar * 20 + ahalf * 8)     = aL0;
            *(uint4*)(nb + AW + ar * 20 + ahalf * 8 + 4) = aL1;
            *(uint4*)(nb + 2 * AW + br * 20 + bq * 4)      = bH;
            *(uint4*)(nb + 2 * AW + BW + br * 20 + bq * 4) = bL;
        }
        __syncthreads();
    }

    float* sO = (float*)smw;
#pragma unroll
    for (int ii = 0; ii < 2; ii++)
#pragma unroll
        for (int jj = 0; jj < 4; jj++) {
            int r = wi + ii * 16 + (lane >> 2);
            int o = wj + jj * 8 + (lane & 3) * 2;
            float b0v = __ldg(&bc[o]), b1v = __ldg(&bc[o + 1]);
            sO[o * 140 + r]           = leaky(acc[ii][jj][0] + b0v);
            sO[(o + 1) * 140 + r]     = leaky(acc[ii][jj][1] + b1v);
            sO[o * 140 + r + 8]       = leaky(acc[ii][jj][2] + b0v);
            sO[(o + 1) * 140 + r + 8] = leaky(acc[ii][jj][3] + b1v);
        }
    __syncthreads();

    int oo = tid >> 2, c4 = (tid & 3) * 4;
    float* orow = out + (size_t)b * (OUTC * NN) + (size_t)oo * NN + n0;
#pragma unroll
    for (int q = 0; q < 8; q++) {
        float4 v = *(float4*)&sO[oo * 140 + c4 + q * 16];
        *(float4*)&orow[c4 + q * 16] = v;
    }
}

extern "C" void kernel_launch(void* const* d_in, const int* in_sizes, int n_in,
                              void* d_out, int out_size) {
    const float* xyz  = (const float*)d_in[0];
    const float* feat = (const float*)d_in[1];
    const float* W1 = (const float*)d_in[2];
    const float* b1 = (const float*)d_in[3];
    const float* W2 = (const float*)d_in[4];
    const float* b2 = (const float*)d_in[5];
    const float* W3 = (const float*)d_in[6];
    const float* b3 = (const float*)d_in[7];
    const float* Wc = (const float*)d_in[8];
    const float* bc = (const float*)d_in[9];

    float* out = (float*)d_out;
    float* out_main = out;
    const int xyz_elems = BB * NN * 3;
    const int out_elems = BB * OUTC * NN;
    if (out_size == xyz_elems + out_elems) {
        cudaMemcpyAsync(out, xyz, (size_t)xyz_elems * sizeof(float), cudaMemcpyDeviceToDevice);
        out_main = out + xyz_elems;
    }

    transpose_kernel<<<dim3(NN / 32, CC / 32, BB), dim3(32, 8)>>>(feat);
    wcperm_kernel<<<(OUTC * 512) / 256, 256>>>(Wc);

    cudaFuncSetAttribute(knn_kernel, cudaFuncAttributeMaxDynamicSharedMemorySize, (int)KNN_SMEM);
    knn_kernel<<<dim3(NN / 32, BB), 256, KNN_SMEM>>>(xyz);

    projgen_kernel<<<(BB * NN) / (8 * CW), 256>>>(W1, b1, W2, b2, W3, b3);

    cudaFuncSetAttribute(gemm_bf16_kernel, cudaFuncAttributeMaxDynamicSharedMemorySize, GEMM_SMEM_BYTES);
    gemm_bf16_kernel<<<(BB * NN) / 128, 256, GEMM_SMEM_BYTES>>>(bc, out_main);
}

// round 7
// speedup vs baseline: 2.9049x; 1.0846x over previous
#include <cuda_runtime.h>
#include <cuda_bf16.h>
#include <cstdint>

#define BB 8
#define NN 4096
#define CC 64
#define OUTC 64
#define NS 32
#define R2C 0.04f
#define ALPHA 0.2f
#define CAPK 224
// full float bits of 0.0225f (= 0.15^2), exact tight threshold on the d2 word
#define TIGHT32 0x3CB850EBu
#define TIGHTKEY64 ((unsigned long long)TIGHT32 << 32)

// ---- device scratch (allocation-free rule) ----
__device__ float g_featT[(size_t)BB * NN * CC];                 // (B,N,C) 8 MB
__device__ __nv_bfloat16 g_projLb[(size_t)BB * NN * 2048];      // per row: hi[1024], lo[1024] (kc-major)
__device__ __nv_bfloat16 g_WcPb[(size_t)OUTC * 2048];           // per row: hi[1024], lo[1024]
__device__ int   g_idx[(size_t)BB * NN * NS];
__device__ float g_gx [(size_t)BB * NN * NS];
__device__ float g_gy [(size_t)BB * NN * NS];
__device__ float g_gz [(size_t)BB * NN * NS];

__device__ __forceinline__ float leaky(float x) { return fmaxf(x, ALPHA * x); }

__device__ __forceinline__ uint32_t pack_hi(float v0, float v1, float& r0, float& r1) {
    __nv_bfloat16 h0 = __float2bfloat16_rn(v0);
    __nv_bfloat16 h1 = __float2bfloat16_rn(v1);
    r0 = v0 - __bfloat162float(h0);
    r1 = v1 - __bfloat162float(h1);
    uint16_t u0 = *(uint16_t*)&h0, u1 = *(uint16_t*)&h1;
    return ((uint32_t)u1 << 16) | u0;
}
__device__ __forceinline__ uint32_t pack_bf2(float v0, float v1) {
    __nv_bfloat16 h0 = __float2bfloat16_rn(v0);
    __nv_bfloat16 h1 = __float2bfloat16_rn(v1);
    uint16_t u0 = *(uint16_t*)&h0, u1 = *(uint16_t*)&h1;
    return ((uint32_t)u1 << 16) | u0;
}

__device__ __forceinline__ void mma_bf16(float* c, const uint32_t* a, const uint32_t* b) {
    asm volatile(
        "mma.sync.aligned.m16n8k16.row.col.f32.bf16.bf16.f32 "
        "{%0,%1,%2,%3}, {%4,%5,%6,%7}, {%8,%9}, {%0,%1,%2,%3};"
        : "+f"(c[0]), "+f"(c[1]), "+f"(c[2]), "+f"(c[3])
        : "r"(a[0]), "r"(a[1]), "r"(a[2]), "r"(a[3]), "r"(b[0]), "r"(b[1]));
}

// ---------------- dummy: phase-shifter so ncu's captured slot lands on knn ----------------
__global__ void dummy_kernel() {}

// ---------------- transpose: (B,C,N) -> (B,N,C) ----------------
__global__ void transpose_kernel(const float* __restrict__ feat) {
    __shared__ float tile[32][33];
    int b = blockIdx.z, n0 = blockIdx.x * 32, c0 = blockIdx.y * 32;
    int tx = threadIdx.x, ty = threadIdx.y;
    const float* fb = feat + (size_t)b * CC * NN;
    float* ob = g_featT + (size_t)b * NN * CC;
#pragma unroll
    for (int i = 0; i < 4; i++)
        tile[ty + i * 8][tx] = fb[(size_t)(c0 + ty + i * 8) * NN + n0 + tx];
    __syncthreads();
#pragma unroll
    for (int i = 0; i < 4; i++)
        ob[(size_t)(n0 + ty + i * 8) * CC + c0 + tx] = tile[tx][ty + i * 8];
}

// ---------------- Wc permute + bf16 split ----------------
__global__ void wcperm_kernel(const float* __restrict__ Wc) {
    int idx = blockIdx.x * 256 + threadIdx.x;   // 32768 pairs
    int o = idx >> 9, pair = idx & 511;
    int kc0 = pair * 2;
    int c = kc0 & 63, k = kc0 >> 6;
    float x0 = Wc[o * 1024 + c * 16 + k];
    float x1 = Wc[o * 1024 + (c + 1) * 16 + k];
    float r0, r1;
    uint32_t hw = pack_hi(x0, x1, r0, r1);
    uint32_t lw = pack_bf2(r0, r1);
    uint32_t* row = (uint32_t*)(g_WcPb + (size_t)o * 2048);
    row[pair] = hw;
    row[512 + pair] = lw;
}

// ---------------- KNN: atomic-counter scan + tight-filtered rank selection ----------------
// smem: sx,sy,sz[4096] (48KB) + cand u64 [8 warps][4 centers][CAPK] (56KB) + counters
#define KNN_SMEM (size_t)(3 * NN * 4 + 8 * 4 * CAPK * 8 + 8 * 4 * 4)

#define RANK_LOOP(cd, Mlen, kk, rr)                                         \
    do {                                                                    \
        if ((Mlen) <= 64) {                                                 \
            for (int q = 0; q < (Mlen); q++) {                              \
                unsigned long long kq = (cd)[q];                            \
                rr[0] += (kq < kk[0]); rr[1] += (kq < kk[1]);               \
            }                                                               \
        } else if ((Mlen) <= 128) {                                         \
            for (int q = 0; q < (Mlen); q++) {                              \
                unsigned long long kq = (cd)[q];                            \
                rr[0] += (kq < kk[0]); rr[1] += (kq < kk[1]);               \
                rr[2] += (kq < kk[2]); rr[3] += (kq < kk[3]);               \
            }                                                               \
        } else {                                                            \
            for (int q = 0; q < (Mlen); q++) {                              \
                unsigned long long kq = (cd)[q];                            \
                rr[0] += (kq < kk[0]); rr[1] += (kq < kk[1]);               \
                rr[2] += (kq < kk[2]); rr[3] += (kq < kk[3]);               \
                rr[4] += (kq < kk[4]); rr[5] += (kq < kk[5]);               \
                rr[6] += (kq < kk[6]);                                      \
            }                                                               \
        }                                                                   \
    } while (0)

__global__ __launch_bounds__(256, 2) void knn_kernel(const float* __restrict__ xyz) {
    extern __shared__ char smem_raw[];
    float* sx = (float*)smem_raw;
    float* sy = sx + NN;
    float* sz = sy + NN;
    unsigned long long* candAll = (unsigned long long*)(sz + NN);
    int* scnt = (int*)(candAll + 8 * 4 * CAPK);

    int b = blockIdx.y, tid = threadIdx.x, w = tid >> 5, lane = tid & 31;
    const float* xb = xyz + (size_t)b * NN * 3;
    for (int i = tid; i < NN; i += 256) {
        sx[i] = xb[i * 3 + 0];
        sy[i] = xb[i * 3 + 1];
        sz[i] = xb[i * 3 + 2];
    }
    if (tid < 32) scnt[tid] = 0;
    __syncthreads();

    int nbase = blockIdx.x * 32 + w * 4;
    unsigned long long* cand0 = candAll + (size_t)w * 4 * CAPK;
    int* mycnt = scnt + w * 4;
    float cx[4], cy[4], cz[4];
#pragma unroll
    for (int i = 0; i < 4; i++) {
        cx[i] = sx[nbase + i]; cy[i] = sy[nbase + i]; cz[i] = sz[nbase + i];
    }

    // ballot-free scan: smem atomic counter per (warp, center)
    for (int j = lane; j < NN; j += 32) {
        float px = sx[j], py = sy[j], pz = sz[j];
#pragma unroll
        for (int i = 0; i < 4; i++) {
            float dx = px - cx[i], dy = py - cy[i], dz = pz - cz[i];
            float d2 = fmaf(dx, dx, fmaf(dy, dy, dz * dz));
            if (d2 <= R2C) {
                int pos = atomicAdd(&mycnt[i], 1);
                if (pos < CAPK)
                    cand0[i * CAPK + pos] =
                        ((unsigned long long)__float_as_uint(d2) << 32) | (unsigned)j;
            }
        }
    }
    __syncwarp();

#pragma unroll
    for (int i = 0; i < 4; i++) {
        int n = nbase + i;
        size_t cg = (size_t)b * NN + n;
        int M = min(mycnt[i], CAPK);
        unsigned long long* cd = cand0 + i * CAPK;
        unsigned lmask = (1u << lane) - 1u;

        // slots >= M get self (gxyz = 0); only happens when M < 32
        if (lane >= M) {
            g_idx[cg * NS + lane] = n;
            g_gx[cg * NS + lane] = 0.0f;
            g_gy[cg * NS + lane] = 0.0f;
            g_gz[cg * NS + lane] = 0.0f;
        }

        unsigned long long k[7];
#pragma unroll
        for (int t = 0; t < 7; t++) {
            int p = lane + 32 * t;
            k[t] = (p < M) ? cd[p] : ~0ull;
        }
        unsigned bms[7];
        int Mt = 0;
#pragma unroll
        for (int t = 0; t < 7; t++) {
            bms[t] = __ballot_sync(0xffffffffu, k[t] < TIGHTKEY64);
            Mt += __popc(bms[t]);
        }

        if (Mt >= NS) {
            int base = 0;
#pragma unroll
            for (int t = 0; t < 7; t++) {
                if (k[t] < TIGHTKEY64)
                    cd[base + __popc(bms[t] & lmask)] = k[t];
                base += __popc(bms[t]);
            }
            __syncwarp();
            unsigned long long k2[7];
            int rr[7];
#pragma unroll
            for (int t = 0; t < 7; t++) {
                int p = lane + 32 * t;
                k2[t] = (p < Mt) ? cd[p] : ~0ull;
                rr[t] = 0;
            }
            RANK_LOOP(cd, Mt, k2, rr);
#pragma unroll
            for (int t = 0; t < 7; t++) {
                int p = lane + 32 * t;
                if (p < Mt && rr[t] < NS) {
                    int jj = (int)(k2[t] & 0xffffffffull);
                    g_idx[cg * NS + rr[t]] = jj;
                    g_gx[cg * NS + rr[t]] = sx[jj] - cx[i];
                    g_gy[cg * NS + rr[t]] = sy[jj] - cy[i];
                    g_gz[cg * NS + rr[t]] = sz[jj] - cz[i];
                }
            }
        } else {
            int rr[7];
#pragma unroll
            for (int t = 0; t < 7; t++) rr[t] = 0;
            RANK_LOOP(cd, M, k, rr);
#pragma unroll
            for (int t = 0; t < 7; t++) {
                int p = lane + 32 * t;
                if (p < M && rr[t] < NS) {
                    int jj = (int)(k[t] & 0xffffffffull);
                    g_idx[cg * NS + rr[t]] = jj;
                    g_gx[cg * NS + rr[t]] = sx[jj] - cx[i];
                    g_gy[cg * NS + rr[t]] = sy[jj] - cy[i];
                    g_gz[cg * NS + rr[t]] = sz[jj] - cz[i];
                }
            }
        }
        __syncwarp();
    }
}

// ---------------- projgen: MLP + normalize + rank-32 proj, bf16-split output ----------------
#define CW 2
__global__ __launch_bounds__(256) void projgen_kernel(
    const float* __restrict__ W1, const float* __restrict__ b1,
    const float* __restrict__ W2, const float* __restrict__ b2,
    const float* __restrict__ W3, const float* __restrict__ b3)
{
    __shared__ float swfAll[8][512];
    __shared__ int   snjAll[8][32];
    __shared__ float sW[448];

    int tid = threadIdx.x, w = tid >> 5, lane = tid & 31;
    if (tid < 24)  sW[tid] = W1[tid];
    if (tid < 8)   sW[24 + tid] = b1[tid];
    if (tid < 128) sW[32 + tid] = W2[tid];
    if (tid < 16)  sW[160 + tid] = b2[tid];
    sW[176 + tid] = W3[tid];
    if (tid < 16)  sW[432 + tid] = b3[tid];
    __syncthreads();

    float* swf = swfAll[w];
    int* snj = snjAll[w];

    for (int it = 0; it < CW; it++) {
        size_t cg = (size_t)blockIdx.x * (8 * CW) + w * CW + it;
        int bb = (int)(cg >> 12);

        int   nj = g_idx[cg * NS + lane];
        float gx = g_gx[cg * NS + lane];
        float gy = g_gy[cg * NS + lane];
        float gz = g_gz[cg * NS + lane];

        float h1[8];
#pragma unroll
        for (int o = 0; o < 8; o++)
            h1[o] = leaky(fmaf(sW[o*3+0], gx, fmaf(sW[o*3+1], gy, fmaf(sW[o*3+2], gz, sW[24+o]))));
        float h2[16];
#pragma unroll
        for (int o = 0; o < 16; o++) {
            float a = sW[160 + o];
#pragma unroll
            for (int i = 0; i < 8; i++) a = fmaf(sW[32 + o*8 + i], h1[i], a);
            h2[o] = leaky(a);
        }
        float wv[16], w2sum = 0.0f;
#pragma unroll
        for (int o = 0; o < 16; o++) {
            float a = sW[432 + o];
#pragma unroll
            for (int i = 0; i < 16; i++) a = fmaf(sW[176 + o*16 + i], h2[i], a);
            wv[o] = a; w2sum = fmaf(a, a, w2sum);
        }
        float inv1 = rsqrtf(fmaxf(w2sum, 1e-8f));

        float wn[16];
#pragma unroll
        for (int kk = 0; kk < 16; kk++) {
            float t = wv[kk] * wv[kk];
#pragma unroll
            for (int off = 16; off; off >>= 1) t += __shfl_xor_sync(0xffffffffu, t, off);
            float s2 = fmaxf(sqrtf(fmaxf(t, 1e-8f)), 1.0f);
            wn[kk] = wv[kk] * inv1 * (1.0f / s2);
        }

        float4* swf4 = (float4*)swf;
#pragma unroll
        for (int q = 0; q < 4; q++)
            swf4[q * 32 + lane] = make_float4(wn[4*q], wn[4*q+1], wn[4*q+2], wn[4*q+3]);
        snj[lane] = nj;
        __syncwarp();

        const float* fT = g_featT + (size_t)bb * NN * CC;
        float2 buf[8];
#pragma unroll
        for (int p = 0; p < 8; p++)
            buf[p] = *(const float2*)(fT + (size_t)snj[p] * CC + 2 * lane);

        float acc0[16], acc1[16];
#pragma unroll
        for (int kk = 0; kk < 16; kk++) { acc0[kk] = 0.0f; acc1[kk] = 0.0f; }

#pragma unroll
        for (int s = 0; s < 32; s++) {
            float2 f = buf[s & 7];
            if (s < 24)
                buf[s & 7] = *(const float2*)(fT + (size_t)snj[s + 8] * CC + 2 * lane);
            float4 q0 = swf4[s], q1 = swf4[32 + s], q2 = swf4[64 + s], q3 = swf4[96 + s];
            acc0[0]  = fmaf(q0.x, f.x, acc0[0]);  acc1[0]  = fmaf(q0.x, f.y, acc1[0]);
            acc0[1]  = fmaf(q0.y, f.x, acc0[1]);  acc1[1]  = fmaf(q0.y, f.y, acc1[1]);
            acc0[2]  = fmaf(q0.z, f.x, acc0[2]);  acc1[2]  = fmaf(q0.z, f.y, acc1[2]);
            acc0[3]  = fmaf(q0.w, f.x, acc0[3]);  acc1[3]  = fmaf(q0.w, f.y, acc1[3]);
            acc0[4]  = fmaf(q1.x, f.x, acc0[4]);  acc1[4]  = fmaf(q1.x, f.y, acc1[4]);
            acc0[5]  = fmaf(q1.y, f.x, acc0[5]);  acc1[5]  = fmaf(q1.y, f.y, acc1[5]);
            acc0[6]  = fmaf(q1.z, f.x, acc0[6]);  acc1[6]  = fmaf(q1.z, f.y, acc1[6]);
            acc0[7]  = fmaf(q1.w, f.x, acc0[7]);  acc1[7]  = fmaf(q1.w, f.y, acc1[7]);
            acc0[8]  = fmaf(q2.x, f.x, acc0[8]);  acc1[8]  = fmaf(q2.x, f.y, acc1[8]);
            acc0[9]  = fmaf(q2.y, f.x, acc0[9]);  acc1[9]  = fmaf(q2.y, f.y, acc1[9]);
            acc0[10] = fmaf(q2.z, f.x, acc0[10]); acc1[10] = fmaf(q2.z, f.y, acc1[10]);
            acc0[11] = fmaf(q2.w, f.x, acc0[11]); acc1[11] = fmaf(q2.w, f.y, acc1[11]);
            acc0[12] = fmaf(q3.x, f.x, acc0[12]); acc1[12] = fmaf(q3.x, f.y, acc1[12]);
            acc0[13] = fmaf(q3.y, f.x, acc0[13]); acc1[13] = fmaf(q3.y, f.y, acc1[13]);
            acc0[14] = fmaf(q3.z, f.x, acc0[14]); acc1[14] = fmaf(q3.z, f.y, acc1[14]);
            acc0[15] = fmaf(q3.w, f.x, acc0[15]); acc1[15] = fmaf(q3.w, f.y, acc1[15]);
        }

        uint32_t* row = (uint32_t*)(g_projLb + cg * 2048);
#pragma unroll
        for (int kk = 0; kk < 16; kk++) {
            float v0 = leaky(acc0[kk]), v1 = leaky(acc1[kk]);
            float r0, r1;
            uint32_t hw = pack_hi(v0, v1, r0, r1);
            uint32_t lw = pack_bf2(r0, r1);
            row[kk * 32 + lane] = hw;
            row[512 + kk * 32 + lane] = lw;
        }
        __syncwarp();
    }
}

// ---------------- GEMM (bf16 hi/lo split, m16n8k16) ----------------
#define AW (128 * 20)
#define BW (64 * 20)
#define STGW (2 * AW + 2 * BW)
#define GEMM_SMEM_BYTES (2 * STGW * 4)

__global__ __launch_bounds__(256) void gemm_bf16_kernel(
    const float* __restrict__ bc, float* __restrict__ out)
{
    extern __shared__ uint32_t smw[];
    int tid = threadIdx.x, lane = tid & 31, w = tid >> 5;
    size_t row0 = (size_t)blockIdx.x * 128;
    int b = (int)(row0 >> 12), n0 = (int)(row0 & 4095);

    int ar = tid >> 1, ahalf = tid & 1;
    int br = tid >> 2, bq = tid & 3;

    const uint32_t* rowA = (const uint32_t*)(g_projLb + (row0 + ar) * 2048);
    const uint32_t* rowB = (const uint32_t*)(g_WcPb + (size_t)br * 2048);

    int wi = (w & 3) * 32;
    int wj = (w >> 2) * 32;

    float acc[2][4][4];
#pragma unroll
    for (int i = 0; i < 2; i++)
#pragma unroll
        for (int j = 0; j < 4; j++)
#pragma unroll
            for (int q = 0; q < 4; q++) acc[i][j][q] = 0.0f;

    uint4 aH0, aH1, aL0, aL1, bH, bL;
    {
        const uint4* pAh = (const uint4*)(rowA + ahalf * 8);
        const uint4* pAl = (const uint4*)(rowA + 512 + ahalf * 8);
        aH0 = pAh[0]; aH1 = pAh[1]; aL0 = pAl[0]; aL1 = pAl[1];
        bH = *(const uint4*)(rowB + bq * 4);
        bL = *(const uint4*)(rowB + 512 + bq * 4);
    }
    {
        uint32_t* buf = smw;
        *(uint4*)(buf + ar * 20 + ahalf * 8)          = aH0;
        *(uint4*)(buf + ar * 20 + ahalf * 8 + 4)      = aH1;
        *(uint4*)(buf + AW + ar * 20 + ahalf * 8)     = aL0;
        *(uint4*)(buf + AW + ar * 20 + ahalf * 8 + 4) = aL1;
        *(uint4*)(buf + 2 * AW + br * 20 + bq * 4)          = bH;
        *(uint4*)(buf + 2 * AW + BW + br * 20 + bq * 4)     = bL;
    }
    __syncthreads();

    for (int s = 0; s < 32; s++) {
        if (s + 1 < 32) {
            int wb = (s + 1) * 16;
            const uint4* pAh = (const uint4*)(rowA + wb + ahalf * 8);
            const uint4* pAl = (const uint4*)(rowA + 512 + wb + ahalf * 8);
            aH0 = pAh[0]; aH1 = pAh[1]; aL0 = pAl[0]; aL1 = pAl[1];
            bH = *(const uint4*)(rowB + wb + bq * 4);
            bL = *(const uint4*)(rowB + 512 + wb + bq * 4);
        }
        const uint32_t* buf = smw + (s & 1) * STGW;
        const uint32_t* Ah = buf;
        const uint32_t* Al = buf + AW;
        const uint32_t* Bh = buf + 2 * AW;
        const uint32_t* Bl = buf + 2 * AW + BW;

#pragma unroll
        for (int t = 0; t < 2; t++) {
            int wb = t * 8;
            uint32_t ah[2][4], al[2][4];
#pragma unroll
            for (int ii = 0; ii < 2; ii++) {
                int r = wi + ii * 16 + (lane >> 2);
                int c0 = wb + (lane & 3);
                ah[ii][0] = Ah[r * 20 + c0];
                ah[ii][1] = Ah[(r + 8) * 20 + c0];
                ah[ii][2] = Ah[r * 20 + c0 + 4];
                ah[ii][3] = Ah[(r + 8) * 20 + c0 + 4];
                al[ii][0] = Al[r * 20 + c0];
                al[ii][1] = Al[(r + 8) * 20 + c0];
                al[ii][2] = Al[r * 20 + c0 + 4];
                al[ii][3] = Al[(r + 8) * 20 + c0 + 4];
            }
            uint32_t bh[4][2], bl[4][2];
#pragma unroll
            for (int jj = 0; jj < 4; jj++) {
                int n = wj + jj * 8 + (lane >> 2);
                int c0 = wb + (lane & 3);
                bh[jj][0] = Bh[n * 20 + c0];
                bh[jj][1] = Bh[n * 20 + c0 + 4];
                bl[jj][0] = Bl[n * 20 + c0];
                bl[jj][1] = Bl[n * 20 + c0 + 4];
            }
#pragma unroll
            for (int ii = 0; ii < 2; ii++)
#pragma unroll
                for (int jj = 0; jj < 4; jj++) {
                    mma_bf16(acc[ii][jj], ah[ii], bh[jj]);
                    mma_bf16(acc[ii][jj], ah[ii], bl[jj]);
                    mma_bf16(acc[ii][jj], al[ii], bh[jj]);
                }
        }

        if (s + 1 < 32) {
            uint32_t* nb = smw + ((s + 1) & 1) * STGW;
            *(uint4*)(nb + ar * 20 + ahalf * 8)          = aH0;
            *(uint4*)(nb + ar * 20 + ahalf * 8 + 4)      = aH1;
            *(uint4*)(nb + AW + ar * 20 + ahalf * 8)     = aL0;
            *(uint4*)(nb + AW + ar * 20 + ahalf * 8 + 4) = aL1;
            *(uint4*)(nb + 2 * AW + br * 20 + bq * 4)      = bH;
            *(uint4*)(nb + 2 * AW + BW + br * 20 + bq * 4) = bL;
        }
        __syncthreads();
    }

    float* sO = (float*)smw;
#pragma unroll
    for (int ii = 0; ii < 2; ii++)
#pragma unroll
        for (int jj = 0; jj < 4; jj++) {
            int r = wi + ii * 16 + (lane >> 2);
            int o = wj + jj * 8 + (lane & 3) * 2;
            float b0v = __ldg(&bc[o]), b1v = __ldg(&bc[o + 1]);
            sO[o * 140 + r]           = leaky(acc[ii][jj][0] + b0v);
            sO[(o + 1) * 140 + r]     = leaky(acc[ii][jj][1] + b1v);
            sO[o * 140 + r + 8]       = leaky(acc[ii][jj][2] + b0v);
            sO[(o + 1) * 140 + r + 8] = leaky(acc[ii][jj][3] + b1v);
        }
    __syncthreads();

    int oo = tid >> 2, c4 = (tid & 3) * 4;
    float* orow = out + (size_t)b * (OUTC * NN) + (size_t)oo * NN + n0;
#pragma unroll
    for (int q = 0; q < 8; q++) {
        float4 v = *(float4*)&sO[oo * 140 + c4 + q * 16];
        *(float4*)&orow[c4 + q * 16] = v;
    }
}

extern "C" void kernel_launch(void* const* d_in, const int* in_sizes, int n_in,
                              void* d_out, int out_size) {
    const float* xyz  = (const float*)d_in[0];
    const float* feat = (const float*)d_in[1];
    const float* W1 = (const float*)d_in[2];
    const float* b1 = (const float*)d_in[3];
    const float* W2 = (const float*)d_in[4];
    const float* b2 = (const float*)d_in[5];
    const float* W3 = (const float*)d_in[6];
    const float* b3 = (const float*)d_in[7];
    const float* Wc = (const float*)d_in[8];
    const float* bc = (const float*)d_in[9];

    float* out = (float*)d_out;
    float* out_main = out;
    const int xyz_elems = BB * NN * 3;
    const int out_elems = BB * OUTC * NN;
    if (out_size == xyz_elems + out_elems) {
        cudaMemcpyAsync(out, xyz, (size_t)xyz_elems * sizeof(float), cudaMemcpyDeviceToDevice);
        out_main = out + xyz_elems;
    }

    // 6-launch cycle; ncu's captured slot (pos 4) = knn_kernel this round
    transpose_kernel<<<dim3(NN / 32, CC / 32, BB), dim3(32, 8)>>>(feat);      // 1
    wcperm_kernel<<<(OUTC * 512) / 256, 256>>>(Wc);                            // 2
    dummy_kernel<<<1, 32>>>();                                                 // 3

    cudaFuncSetAttribute(knn_kernel, cudaFuncAttributeMaxDynamicSharedMemorySize, (int)KNN_SMEM);
    knn_kernel<<<dim3(NN / 32, BB), 256, KNN_SMEM>>>(xyz);                     // 4

    projgen_kernel<<<(BB * NN) / (8 * CW), 256>>>(W1, b1, W2, b2, W3, b3);     // 5

    cudaFuncSetAttribute(gemm_bf16_kernel, cudaFuncAttributeMaxDynamicSharedMemorySize, GEMM_SMEM_BYTES);
    gemm_bf16_kernel<<<(BB * NN) / 128, 256, GEMM_SMEM_BYTES>>>(bc, out_main); // 6
}

// round 8
// speedup vs baseline: 3.2500x; 1.1188x over previous
#include <cuda_runtime.h>
#include <cuda_bf16.h>
#include <cstdint>

#define BB 8
#define NN 4096
#define CC 64
#define OUTC 64
#define NS 32
#define R2C 0.04f
#define ALPHA 0.2f
#define CAPK 224
#define NCELL 1000
// full float bits of 0.0225f (= 0.15^2), exact tight threshold on the d2 word
#define TIGHT32 0x3CB850EBu
#define TIGHTKEY64 ((unsigned long long)TIGHT32 << 32)

// ---- device scratch (allocation-free rule) ----
__device__ float g_featT[(size_t)BB * NN * CC];                 // (B,N,C) 8 MB
__device__ __nv_bfloat16 g_projLb[(size_t)BB * NN * 2048];      // per row: hi[1024], lo[1024]
__device__ __nv_bfloat16 g_WcPb[(size_t)OUTC * 2048];           // per row: hi[1024], lo[1024]
__device__ int   g_idx[(size_t)BB * NN * NS];
__device__ float g_gx [(size_t)BB * NN * NS];
__device__ float g_gy [(size_t)BB * NN * NS];
__device__ float g_gz [(size_t)BB * NN * NS];
__device__ float4 g_pts4[(size_t)BB * NN];                      // cell-sorted {x,y,z,origIdx}
__device__ int   g_cellStart[(size_t)BB * (NCELL + 1)];

__device__ __forceinline__ float leaky(float x) { return fmaxf(x, ALPHA * x); }

__device__ __forceinline__ uint32_t pack_hi(float v0, float v1, float& r0, float& r1) {
    __nv_bfloat16 h0 = __float2bfloat16_rn(v0);
    __nv_bfloat16 h1 = __float2bfloat16_rn(v1);
    r0 = v0 - __bfloat162float(h0);
    r1 = v1 - __bfloat162float(h1);
    uint16_t u0 = *(uint16_t*)&h0, u1 = *(uint16_t*)&h1;
    return ((uint32_t)u1 << 16) | u0;
}
__device__ __forceinline__ uint32_t pack_bf2(float v0, float v1) {
    __nv_bfloat16 h0 = __float2bfloat16_rn(v0);
    __nv_bfloat16 h1 = __float2bfloat16_rn(v1);
    uint16_t u0 = *(uint16_t*)&h0, u1 = *(uint16_t*)&h1;
    return ((uint32_t)u1 << 16) | u0;
}

__device__ __forceinline__ void mma_bf16(float* c, const uint32_t* a, const uint32_t* b) {
    asm volatile(
        "mma.sync.aligned.m16n8k16.row.col.f32.bf16.bf16.f32 "
        "{%0,%1,%2,%3}, {%4,%5,%6,%7}, {%8,%9}, {%0,%1,%2,%3};"
        : "+f"(c[0]), "+f"(c[1]), "+f"(c[2]), "+f"(c[3])
        : "r"(a[0]), "r"(a[1]), "r"(a[2]), "r"(a[3]), "r"(b[0]), "r"(b[1]));
}

// ---------------- transpose: (B,C,N) -> (B,N,C) ----------------
__global__ void transpose_kernel(const float* __restrict__ feat) {
    __shared__ float tile[32][33];
    int b = blockIdx.z, n0 = blockIdx.x * 32, c0 = blockIdx.y * 32;
    int tx = threadIdx.x, ty = threadIdx.y;
    const float* fb = feat + (size_t)b * CC * NN;
    float* ob = g_featT + (size_t)b * NN * CC;
#pragma unroll
    for (int i = 0; i < 4; i++)
        tile[ty + i * 8][tx] = fb[(size_t)(c0 + ty + i * 8) * NN + n0 + tx];
    __syncthreads();
#pragma unroll
    for (int i = 0; i < 4; i++)
        ob[(size_t)(n0 + ty + i * 8) * CC + c0 + tx] = tile[tx][ty + i * 8];
}

// ---------------- Wc permute + bf16 split ----------------
__global__ void wcperm_kernel(const float* __restrict__ Wc) {
    int idx = blockIdx.x * 256 + threadIdx.x;   // 32768 pairs
    int o = idx >> 9, pair = idx & 511;
    int kc0 = pair * 2;
    int c = kc0 & 63, k = kc0 >> 6;
    float x0 = Wc[o * 1024 + c * 16 + k];
    float x1 = Wc[o * 1024 + (c + 1) * 16 + k];
    float r0, r1;
    uint32_t hw = pack_hi(x0, x1, r0, r1);
    uint32_t lw = pack_bf2(r0, r1);
    uint32_t* row = (uint32_t*)(g_WcPb + (size_t)o * 2048);
    row[pair] = hw;
    row[512 + pair] = lw;
}

// ---------------- bin: counting sort into 10^3 cells ----------------
__global__ __launch_bounds__(1024) void bin_kernel(const float* __restrict__ xyz) {
    __shared__ int cnt[NCELL];
    __shared__ int off[NCELL];
    __shared__ int wsum[32];
    int b = blockIdx.x, tid = threadIdx.x, lane = tid & 31, wid = tid >> 5;
    for (int i = tid; i < NCELL; i += 1024) cnt[i] = 0;
    __syncthreads();

    float xs[4], ys[4], zs[4];
    int cell[4];
    const float* xb = xyz + (size_t)b * NN * 3;
#pragma unroll
    for (int t = 0; t < 4; t++) {
        int n = tid * 4 + t;
        xs[t] = xb[n * 3 + 0];
        ys[t] = xb[n * 3 + 1];
        zs[t] = xb[n * 3 + 2];
        int ci = min((int)(xs[t] * 10.f), 9);
        int cj = min((int)(ys[t] * 10.f), 9);
        int ck = min((int)(zs[t] * 10.f), 9);
        cell[t] = (ck * 10 + cj) * 10 + ci;
        atomicAdd(&cnt[cell[t]], 1);
    }
    __syncthreads();

    // exclusive scan over NCELL (1024-wide: warp scans + warp0 combine)
    int v = (tid < NCELL) ? cnt[tid] : 0;
    int orig = v;
#pragma unroll
    for (int d = 1; d < 32; d <<= 1) {
        int t2 = __shfl_up_sync(0xffffffffu, v, d);
        if (lane >= d) v += t2;
    }
    if (lane == 31) wsum[wid] = v;
    __syncthreads();
    if (wid == 0) {
        int s = wsum[lane];
#pragma unroll
        for (int d = 1; d < 32; d <<= 1) {
            int t2 = __shfl_up_sync(0xffffffffu, s, d);
            if (lane >= d) s += t2;
        }
        wsum[lane] = s;
    }
    __syncthreads();
    int excl = v + (wid > 0 ? wsum[wid - 1] : 0) - orig;
    if (tid < NCELL) {
        off[tid] = excl;
        g_cellStart[(size_t)b * (NCELL + 1) + tid] = excl;
    }
    if (tid == 0) g_cellStart[(size_t)b * (NCELL + 1) + NCELL] = NN;
    __syncthreads();

#pragma unroll
    for (int t = 0; t < 4; t++) {
        int n = tid * 4 + t;
        int pos = atomicAdd(&off[cell[t]], 1);
        g_pts4[(size_t)b * NN + pos] = make_float4(xs[t], ys[t], zs[t], __int_as_float(n));
    }
}

// ---------------- KNN: binned scan + tight-filtered rank selection ----------------
// smem: cand u64 [8][4][CAPK] (56KB) + cellStart copy (4KB) + counters
#define KNN_SMEM (size_t)(8 * 4 * CAPK * 8 + (NCELL + 8) * 4 + 32 * 4)

#define RANK_LOOP(cd, Mlen, kk, rr)                                         \
    do {                                                                    \
        if ((Mlen) <= 64) {                                                 \
            for (int q = 0; q < (Mlen); q++) {                              \
                unsigned long long kq = (cd)[q];                            \
                rr[0] += (kq < kk[0]); rr[1] += (kq < kk[1]);               \
            }                                                               \
        } else if ((Mlen) <= 128) {                                         \
            for (int q = 0; q < (Mlen); q++) {                              \
                unsigned long long kq = (cd)[q];                            \
                rr[0] += (kq < kk[0]); rr[1] += (kq < kk[1]);               \
                rr[2] += (kq < kk[2]); rr[3] += (kq < kk[3]);               \
            }                                                               \
        } else {                                                            \
            for (int q = 0; q < (Mlen); q++) {                              \
                unsigned long long kq = (cd)[q];                            \
                rr[0] += (kq < kk[0]); rr[1] += (kq < kk[1]);               \
                rr[2] += (kq < kk[2]); rr[3] += (kq < kk[3]);               \
                rr[4] += (kq < kk[4]); rr[5] += (kq < kk[5]);               \
                rr[6] += (kq < kk[6]);                                      \
            }                                                               \
        }                                                                   \
    } while (0)

__global__ __launch_bounds__(256, 3) void knn_kernel(const float* __restrict__ xyz) {
    extern __shared__ char smem_raw[];
    unsigned long long* candAll = (unsigned long long*)smem_raw;
    int* scell = (int*)(candAll + 8 * 4 * CAPK);
    int* scnt = scell + (NCELL + 8);

    int b = blockIdx.y, tid = threadIdx.x, w = tid >> 5, lane = tid & 31;
    const int* cs = g_cellStart + (size_t)b * (NCELL + 1);
    for (int i = tid; i < NCELL + 1; i += 256) scell[i] = cs[i];
    if (tid < 32) scnt[tid] = 0;
    __syncthreads();

    int nbase = blockIdx.x * 32 + w * 4;
    unsigned long long* cand0 = candAll + (size_t)w * 4 * CAPK;
    int* mycnt = scnt + w * 4;
    const float4* pts = g_pts4 + (size_t)b * NN;

    float cx[4], cy[4], cz[4];
#pragma unroll
    for (int i = 0; i < 4; i++) {
        const float* c = xyz + ((size_t)b * NN + nbase + i) * 3;
        cx[i] = __ldg(c + 0); cy[i] = __ldg(c + 1); cz[i] = __ldg(c + 2);
    }

    // binned scan: 25 contiguous (z,y)-row segments per center
#pragma unroll
    for (int i = 0; i < 4; i++) {
        int cxi = min((int)(cx[i] * 10.f), 9);
        int cyi = min((int)(cy[i] * 10.f), 9);
        int czi = min((int)(cz[i] * 10.f), 9);
        int xlo = max(cxi - 2, 0), xhi = min(cxi + 2, 9);
        int ylo = max(cyi - 2, 0), yhi = min(cyi + 2, 9);
        int zlo = max(czi - 2, 0), zhi = min(czi + 2, 9);
        for (int zz = zlo; zz <= zhi; zz++) {
            for (int yy = ylo; yy <= yhi; yy++) {
                int rb = (zz * 10 + yy) * 10;
                int s = scell[rb + xlo], e = scell[rb + xhi + 1];
                for (int p = s + lane; p < e; p += 32) {
                    float4 pt = pts[p];
                    float dx = pt.x - cx[i], dy = pt.y - cy[i], dz = pt.z - cz[i];
                    float d2 = fmaf(dx, dx, fmaf(dy, dy, dz * dz));
                    if (d2 <= R2C) {
                        int pos = atomicAdd(&mycnt[i], 1);
                        if (pos < CAPK)
                            cand0[i * CAPK + pos] =
                                ((unsigned long long)__float_as_uint(d2) << 32) |
                                ((unsigned)__float_as_int(pt.w) << 12) | (unsigned)p;
                    }
                }
            }
        }
    }
    __syncwarp();

#pragma unroll
    for (int i = 0; i < 4; i++) {
        int n = nbase + i;
        size_t cg = (size_t)b * NN + n;
        int M = min(mycnt[i], CAPK);
        unsigned long long* cd = cand0 + i * CAPK;
        unsigned lmask = (1u << lane) - 1u;

        // slots >= M get self (gxyz = 0); only when M < 32
        if (lane >= M) {
            g_idx[cg * NS + lane] = n;
            g_gx[cg * NS + lane] = 0.0f;
            g_gy[cg * NS + lane] = 0.0f;
            g_gz[cg * NS + lane] = 0.0f;
        }

        unsigned long long k[7];
#pragma unroll
        for (int t = 0; t < 7; t++) {
            int p = lane + 32 * t;
            k[t] = (p < M) ? cd[p] : ~0ull;
        }
        unsigned bms[7];
        int Mt = 0;
#pragma unroll
        for (int t = 0; t < 7; t++) {
            bms[t] = __ballot_sync(0xffffffffu, k[t] < TIGHTKEY64);
            Mt += __popc(bms[t]);
        }

        if (Mt >= NS) {
            int base = 0;
#pragma unroll
            for (int t = 0; t < 7; t++) {
                if (k[t] < TIGHTKEY64)
                    cd[base + __popc(bms[t] & lmask)] = k[t];
                base += __popc(bms[t]);
            }
            __syncwarp();
            unsigned long long k2[7];
            int rr[7];
#pragma unroll
            for (int t = 0; t < 7; t++) {
                int p = lane + 32 * t;
                k2[t] = (p < Mt) ? cd[p] : ~0ull;
                rr[t] = 0;
            }
            RANK_LOOP(cd, Mt, k2, rr);
#pragma unroll
            for (int t = 0; t < 7; t++) {
                int p = lane + 32 * t;
                if (p < Mt && rr[t] < NS) {
                    int low = (int)(k2[t] & 0xffffffffull);
                    int jj = (low >> 12) & 0xFFF;
                    float4 p4 = pts[low & 0xFFF];
                    g_idx[cg * NS + rr[t]] = jj;
                    g_gx[cg * NS + rr[t]] = p4.x - cx[i];
                    g_gy[cg * NS + rr[t]] = p4.y - cy[i];
                    g_gz[cg * NS + rr[t]] = p4.z - cz[i];
                }
            }
        } else {
            int rr[7];
#pragma unroll
            for (int t = 0; t < 7; t++) rr[t] = 0;
            RANK_LOOP(cd, M, k, rr);
#pragma unroll
            for (int t = 0; t < 7; t++) {
                int p = lane + 32 * t;
                if (p < M && rr[t] < NS) {
                    int low = (int)(k[t] & 0xffffffffull);
                    int jj = (low >> 12) & 0xFFF;
                    float4 p4 = pts[low & 0xFFF];
                    g_idx[cg * NS + rr[t]] = jj;
                    g_gx[cg * NS + rr[t]] = p4.x - cx[i];
                    g_gy[cg * NS + rr[t]] = p4.y - cy[i];
                    g_gz[cg * NS + rr[t]] = p4.z - cz[i];
                }
            }
        }
        __syncwarp();
    }
}

// ---------------- projgen: MLP + normalize + rank-32 proj, bf16-split output ----------------
#define CW 2
__global__ __launch_bounds__(256) void projgen_kernel(
    const float* __restrict__ W1, const float* __restrict__ b1,
    const float* __restrict__ W2, const float* __restrict__ b2,
    const float* __restrict__ W3, const float* __restrict__ b3)
{
    __shared__ float swfAll[8][512];
    __shared__ int   snjAll[8][32];
    __shared__ float sW[448];

    int tid = threadIdx.x, w = tid >> 5, lane = tid & 31;
    if (tid < 24)  sW[tid] = W1[tid];
    if (tid < 8)   sW[24 + tid] = b1[tid];
    if (tid < 128) sW[32 + tid] = W2[tid];
    if (tid < 16)  sW[160 + tid] = b2[tid];
    sW[176 + tid] = W3[tid];
    if (tid < 16)  sW[432 + tid] = b3[tid];
    __syncthreads();

    float* swf = swfAll[w];
    int* snj = snjAll[w];

    for (int it = 0; it < CW; it++) {
        size_t cg = (size_t)blockIdx.x * (8 * CW) + w * CW + it;
        int bb = (int)(cg >> 12);

        int   nj = g_idx[cg * NS + lane];
        float gx = g_gx[cg * NS + lane];
        float gy = g_gy[cg * NS + lane];
        float gz = g_gz[cg * NS + lane];

        float h1[8];
#pragma unroll
        for (int o = 0; o < 8; o++)
            h1[o] = leaky(fmaf(sW[o*3+0], gx, fmaf(sW[o*3+1], gy, fmaf(sW[o*3+2], gz, sW[24+o]))));
        float h2[16];
#pragma unroll
        for (int o = 0; o < 16; o++) {
            float a = sW[160 + o];
#pragma unroll
            for (int i = 0; i < 8; i++) a = fmaf(sW[32 + o*8 + i], h1[i], a);
            h2[o] = leaky(a);
        }
        float wv[16], w2sum = 0.0f;
#pragma unroll
        for (int o = 0; o < 16; o++) {
            float a = sW[432 + o];
#pragma unroll
            for (int i = 0; i < 16; i++) a = fmaf(sW[176 + o*16 + i], h2[i], a);
            wv[o] = a; w2sum = fmaf(a, a, w2sum);
        }
        float inv1 = rsqrtf(fmaxf(w2sum, 1e-8f));

        float wn[16];
#pragma unroll
        for (int kk = 0; kk < 16; kk++) {
            float t = wv[kk] * wv[kk];
#pragma unroll
            for (int off = 16; off; off >>= 1) t += __shfl_xor_sync(0xffffffffu, t, off);
            float s2 = fmaxf(sqrtf(fmaxf(t, 1e-8f)), 1.0f);
            wn[kk] = wv[kk] * inv1 * (1.0f / s2);
        }

        float4* swf4 = (float4*)swf;
#pragma unroll
        for (int q = 0; q < 4; q++)
            swf4[q * 32 + lane] = make_float4(wn[4*q], wn[4*q+1], wn[4*q+2], wn[4*q+3]);
        snj[lane] = nj;
        __syncwarp();

        const float* fT = g_featT + (size_t)bb * NN * CC;
        float2 buf[8];
#pragma unroll
        for (int p = 0; p < 8; p++)
            buf[p] = *(const float2*)(fT + (size_t)snj[p] * CC + 2 * lane);

        float acc0[16], acc1[16];
#pragma unroll
        for (int kk = 0; kk < 16; kk++) { acc0[kk] = 0.0f; acc1[kk] = 0.0f; }

#pragma unroll
        for (int s = 0; s < 32; s++) {
            float2 f = buf[s & 7];
            if (s < 24)
                buf[s & 7] = *(const float2*)(fT + (size_t)snj[s + 8] * CC + 2 * lane);
            float4 q0 = swf4[s], q1 = swf4[32 + s], q2 = swf4[64 + s], q3 = swf4[96 + s];
            acc0[0]  = fmaf(q0.x, f.x, acc0[0]);  acc1[0]  = fmaf(q0.x, f.y, acc1[0]);
            acc0[1]  = fmaf(q0.y, f.x, acc0[1]);  acc1[1]  = fmaf(q0.y, f.y, acc1[1]);
            acc0[2]  = fmaf(q0.z, f.x, acc0[2]);  acc1[2]  = fmaf(q0.z, f.y, acc1[2]);
            acc0[3]  = fmaf(q0.w, f.x, acc0[3]);  acc1[3]  = fmaf(q0.w, f.y, acc1[3]);
            acc0[4]  = fmaf(q1.x, f.x, acc0[4]);  acc1[4]  = fmaf(q1.x, f.y, acc1[4]);
            acc0[5]  = fmaf(q1.y, f.x, acc0[5]);  acc1[5]  = fmaf(q1.y, f.y, acc1[5]);
            acc0[6]  = fmaf(q1.z, f.x, acc0[6]);  acc1[6]  = fmaf(q1.z, f.y, acc1[6]);
            acc0[7]  = fmaf(q1.w, f.x, acc0[7]);  acc1[7]  = fmaf(q1.w, f.y, acc1[7]);
            acc0[8]  = fmaf(q2.x, f.x, acc0[8]);  acc1[8]  = fmaf(q2.x, f.y, acc1[8]);
            acc0[9]  = fmaf(q2.y, f.x, acc0[9]);  acc1[9]  = fmaf(q2.y, f.y, acc1[9]);
            acc0[10] = fmaf(q2.z, f.x, acc0[10]); acc1[10] = fmaf(q2.z, f.y, acc1[10]);
            acc0[11] = fmaf(q2.w, f.x, acc0[11]); acc1[11] = fmaf(q2.w, f.y, acc1[11]);
            acc0[12] = fmaf(q3.x, f.x, acc0[12]); acc1[12] = fmaf(q3.x, f.y, acc1[12]);
            acc0[13] = fmaf(q3.y, f.x, acc0[13]); acc1[13] = fmaf(q3.y, f.y, acc1[13]);
            acc0[14] = fmaf(q3.z, f.x, acc0[14]); acc1[14] = fmaf(q3.z, f.y, acc1[14]);
            acc0[15] = fmaf(q3.w, f.x, acc0[15]); acc1[15] = fmaf(q3.w, f.y, acc1[15]);
        }

        uint32_t* row = (uint32_t*)(g_projLb + cg * 2048);
#pragma unroll
        for (int kk = 0; kk < 16; kk++) {
            float v0 = leaky(acc0[kk]), v1 = leaky(acc1[kk]);
            float r0, r1;
            uint32_t hw = pack_hi(v0, v1, r0, r1);
            uint32_t lw = pack_bf2(r0, r1);
            row[kk * 32 + lane] = hw;
            row[512 + kk * 32 + lane] = lw;
        }
        __syncwarp();
    }
}

// ---------------- GEMM (bf16 hi/lo split, m16n8k16) ----------------
#define AW (128 * 20)
#define BW (64 * 20)
#define STGW (2 * AW + 2 * BW)
#define GEMM_SMEM_BYTES (2 * STGW * 4)

__global__ __launch_bounds__(256) void gemm_bf16_kernel(
    const float* __restrict__ bc, float* __restrict__ out)
{
    extern __shared__ uint32_t smw[];
    int tid = threadIdx.x, lane = tid & 31, w = tid >> 5;
    size_t row0 = (size_t)blockIdx.x * 128;
    int b = (int)(row0 >> 12), n0 = (int)(row0 & 4095);

    int ar = tid >> 1, ahalf = tid & 1;
    int br = tid >> 2, bq = tid & 3;

    const uint32_t* rowA = (const uint32_t*)(g_projLb + (row0 + ar) * 2048);
    const uint32_t* rowB = (const uint32_t*)(g_WcPb + (size_t)br * 2048);

    int wi = (w & 3) * 32;
    int wj = (w >> 2) * 32;

    float acc[2][4][4];
#pragma unroll
    for (int i = 0; i < 2; i++)
#pragma unroll
        for (int j = 0; j < 4; j++)
#pragma unroll
            for (int q = 0; q < 4; q++) acc[i][j][q] = 0.0f;

    uint4 aH0, aH1, aL0, aL1, bH, bL;
    {
        const uint4* pAh = (const uint4*)(rowA + ahalf * 8);
        const uint4* pAl = (const uint4*)(rowA + 512 + ahalf * 8);
        aH0 = pAh[0]; aH1 = pAh[1]; aL0 = pAl[0]; aL1 = pAl[1];
        bH = *(const uint4*)(rowB + bq * 4);
        bL = *(const uint4*)(rowB + 512 + bq * 4);
    }
    {
        uint32_t* buf = smw;
        *(uint4*)(buf + ar * 20 + ahalf * 8)          = aH0;
        *(uint4*)(buf + ar * 20 + ahalf * 8 + 4)      = aH1;
        *(uint4*)(buf + AW + ar * 20 + ahalf * 8)     = aL0;
        *(uint4*)(buf + AW + ar * 20 + ahalf * 8 + 4) = aL1;
        *(uint4*)(buf + 2 * AW + br * 20 + bq * 4)          = bH;
        *(uint4*)(buf + 2 * AW + BW + br * 20 + bq * 4)     = bL;
    }
    __syncthreads();

    for (int s = 0; s < 32; s++) {
        if (s + 1 < 32) {
            int wb = (s + 1) * 16;
            const uint4* pAh = (const uint4*)(rowA + wb + ahalf * 8);
            const uint4* pAl = (const uint4*)(rowA + 512 + wb + ahalf * 8);
            aH0 = pAh[0]; aH1 = pAh[1]; aL0 = pAl[0]; aL1 = pAl[1];
            bH = *(const uint4*)(rowB + wb + bq * 4);
            bL = *(const uint4*)(rowB + 512 + wb + bq * 4);
        }
        const uint32_t* buf = smw + (s & 1) * STGW;
        const uint32_t* Ah = buf;
        const uint32_t* Al = buf + AW;
        const uint32_t* Bh = buf + 2 * AW;
        const uint32_t* Bl = buf + 2 * AW + BW;

#pragma unroll
        for (int t = 0; t < 2; t++) {
            int wb = t * 8;
            uint32_t ah[2][4], al[2][4];
#pragma unroll
            for (int ii = 0; ii < 2; ii++) {
                int r = wi + ii * 16 + (lane >> 2);
                int c0 = wb + (lane & 3);
                ah[ii][0] = Ah[r * 20 + c0];
                ah[ii][1] = Ah[(r + 8) * 20 + c0];
                ah[ii][2] = Ah[r * 20 + c0 + 4];
                ah[ii][3] = Ah[(r + 8) * 20 + c0 + 4];
                al[ii][0] = Al[r * 20 + c0];
                al[ii][1] = Al[(r + 8) * 20 + c0];
                al[ii][2] = Al[r * 20 + c0 + 4];
                al[ii][3] = Al[(r + 8) * 20 + c0 + 4];
            }
            uint32_t bh[4][2], bl[4][2];
#pragma unroll
            for (int jj = 0; jj < 4; jj++) {
                int n = wj + jj * 8 + (lane >> 2);
                int c0 = wb + (lane & 3);
                bh[jj][0] = Bh[n * 20 + c0];
                bh[jj][1] = Bh[n * 20 + c0 + 4];
                bl[jj][0] = Bl[n * 20 + c0];
                bl[jj][1] = Bl[n * 20 + c0 + 4];
            }
#pragma unroll
            for (int ii = 0; ii < 2; ii++)
#pragma unroll
                for (int jj = 0; jj < 4; jj++) {
                    mma_bf16(acc[ii][jj], ah[ii], bh[jj]);
                    mma_bf16(acc[ii][jj], ah[ii], bl[jj]);
                    mma_bf16(acc[ii][jj], al[ii], bh[jj]);
                }
        }

        if (s + 1 < 32) {
            uint32_t* nb = smw + ((s + 1) & 1) * STGW;
            *(uint4*)(nb + ar * 20 + ahalf * 8)          = aH0;
            *(uint4*)(nb + ar * 20 + ahalf * 8 + 4)      = aH1;
            *(uint4*)(nb + AW + ar * 20 + ahalf * 8)     = aL0;
            *(uint4*)(nb + AW + ar * 20 + ahalf * 8 + 4) = aL1;
            *(uint4*)(nb + 2 * AW + br * 20 + bq * 4)      = bH;
            *(uint4*)(nb + 2 * AW + BW + br * 20 + bq * 4) = bL;
        }
        __syncthreads();
    }

    float* sO = (float*)smw;
#pragma unroll
    for (int ii = 0; ii < 2; ii++)
#pragma unroll
        for (int jj = 0; jj < 4; jj++) {
            int r = wi + ii * 16 + (lane >> 2);
            int o = wj + jj * 8 + (lane & 3) * 2;
            float b0v = __ldg(&bc[o]), b1v = __ldg(&bc[o + 1]);
            sO[o * 140 + r]           = leaky(acc[ii][jj][0] + b0v);
            sO[(o + 1) * 140 + r]     = leaky(acc[ii][jj][1] + b1v);
            sO[o * 140 + r + 8]       = leaky(acc[ii][jj][2] + b0v);
            sO[(o + 1) * 140 + r + 8] = leaky(acc[ii][jj][3] + b1v);
        }
    __syncthreads();

    int oo = tid >> 2, c4 = (tid & 3) * 4;
    float* orow = out + (size_t)b * (OUTC * NN) + (size_t)oo * NN + n0;
#pragma unroll
    for (int q = 0; q < 8; q++) {
        float4 v = *(float4*)&sO[oo * 140 + c4 + q * 16];
        *(float4*)&orow[c4 + q * 16] = v;
    }
}

extern "C" void kernel_launch(void* const* d_in, const int* in_sizes, int n_in,
                              void* d_out, int out_size) {
    const float* xyz  = (const float*)d_in[0];
    const float* feat = (const float*)d_in[1];
    const float* W1 = (const float*)d_in[2];
    const float* b1 = (const float*)d_in[3];
    const float* W2 = (const float*)d_in[4];
    const float* b2 = (const float*)d_in[5];
    const float* W3 = (const float*)d_in[6];
    const float* b3 = (const float*)d_in[7];
    const float* Wc = (const float*)d_in[8];
    const float* bc = (const float*)d_in[9];

    float* out = (float*)d_out;
    float* out_main = out;
    const int xyz_elems = BB * NN * 3;
    const int out_elems = BB * OUTC * NN;
    if (out_size == xyz_elems + out_elems) {
        cudaMemcpyAsync(out, xyz, (size_t)xyz_elems * sizeof(float), cudaMemcpyDeviceToDevice);
        out_main = out + xyz_elems;
    }

    // ncu captures global launch index 3 -> knn_kernel
    transpose_kernel<<<dim3(NN / 32, CC / 32, BB), dim3(32, 8)>>>(feat);      // 0
    wcperm_kernel<<<(OUTC * 512) / 256, 256>>>(Wc);                            // 1
    bin_kernel<<<BB, 1024>>>(xyz);                                             // 2

    cudaFuncSetAttribute(knn_kernel, cudaFuncAttributeMaxDynamicSharedMemorySize, (int)KNN_SMEM);
    knn_kernel<<<dim3(NN / 32, BB), 256, KNN_SMEM>>>(xyz);                     // 3

    projgen_kernel<<<(BB * NN) / (8 * CW), 256>>>(W1, b1, W2, b2, W3, b3);     // 4

    cudaFuncSetAttribute(gemm_bf16_kernel, cudaFuncAttributeMaxDynamicSharedMemorySize, GEMM_SMEM_BYTES);
    gemm_bf16_kernel<<<(BB * NN) / 128, 256, GEMM_SMEM_BYTES>>>(bc, out_main); // 5
}

// round 9
// speedup vs baseline: 3.6029x; 1.1086x over previous
#include <cuda_runtime.h>
#include <cuda_bf16.h>
#include <cstdint>

#define BB 8
#define NN 4096
#define CC 64
#define OUTC 64
#define NS 32
#define R2C 0.04f
#define ALPHA 0.2f
#define CAPK 224
#define NCELL 1000
// full float bits of 0.0225f (= 0.15^2), exact tight threshold on the d2 word
#define TIGHT32 0x3CB850EBu
#define TIGHTKEY64 ((unsigned long long)TIGHT32 << 32)

// ---- device scratch (allocation-free rule) ----
__device__ float g_featT[(size_t)BB * NN * CC];                 // (B,N,C) 8 MB
__device__ __nv_bfloat16 g_projLb[(size_t)BB * NN * 2048];      // per row: hi[1024], lo[1024]
__device__ __nv_bfloat16 g_WcPb[(size_t)OUTC * 2048];           // per row: hi[1024], lo[1024]
__device__ int   g_idx[(size_t)BB * NN * NS];
__device__ float g_gx [(size_t)BB * NN * NS];
__device__ float g_gy [(size_t)BB * NN * NS];
__device__ float g_gz [(size_t)BB * NN * NS];
__device__ float4 g_pts4[(size_t)BB * NN];                      // cell-sorted {x,y,z,origIdx}
__device__ int   g_cellStart[(size_t)BB * (NCELL + 1)];

__device__ __forceinline__ float leaky(float x) { return fmaxf(x, ALPHA * x); }

__device__ __forceinline__ uint32_t pack_hi(float v0, float v1, float& r0, float& r1) {
    __nv_bfloat16 h0 = __float2bfloat16_rn(v0);
    __nv_bfloat16 h1 = __float2bfloat16_rn(v1);
    r0 = v0 - __bfloat162float(h0);
    r1 = v1 - __bfloat162float(h1);
    uint16_t u0 = *(uint16_t*)&h0, u1 = *(uint16_t*)&h1;
    return ((uint32_t)u1 << 16) | u0;
}
__device__ __forceinline__ uint32_t pack_bf2(float v0, float v1) {
    __nv_bfloat16 h0 = __float2bfloat16_rn(v0);
    __nv_bfloat16 h1 = __float2bfloat16_rn(v1);
    uint16_t u0 = *(uint16_t*)&h0, u1 = *(uint16_t*)&h1;
    return ((uint32_t)u1 << 16) | u0;
}

__device__ __forceinline__ void mma_bf16(float* c, const uint32_t* a, const uint32_t* b) {
    asm volatile(
        "mma.sync.aligned.m16n8k16.row.col.f32.bf16.bf16.f32 "
        "{%0,%1,%2,%3}, {%4,%5,%6,%7}, {%8,%9}, {%0,%1,%2,%3};"
        : "+f"(c[0]), "+f"(c[1]), "+f"(c[2]), "+f"(c[3])
        : "r"(a[0]), "r"(a[1]), "r"(a[2]), "r"(a[3]), "r"(b[0]), "r"(b[1]));
}

// ---------------- transpose: (B,C,N) -> (B,N,C) ----------------
__global__ void transpose_kernel(const float* __restrict__ feat) {
    __shared__ float tile[32][33];
    int b = blockIdx.z, n0 = blockIdx.x * 32, c0 = blockIdx.y * 32;
    int tx = threadIdx.x, ty = threadIdx.y;
    const float* fb = feat + (size_t)b * CC * NN;
    float* ob = g_featT + (size_t)b * NN * CC;
#pragma unroll
    for (int i = 0; i < 4; i++)
        tile[ty + i * 8][tx] = fb[(size_t)(c0 + ty + i * 8) * NN + n0 + tx];
    __syncthreads();
#pragma unroll
    for (int i = 0; i < 4; i++)
        ob[(size_t)(n0 + ty + i * 8) * CC + c0 + tx] = tile[tx][ty + i * 8];
}

// ---------------- Wc permute + bf16 split ----------------
__global__ void wcperm_kernel(const float* __restrict__ Wc) {
    int idx = blockIdx.x * 256 + threadIdx.x;   // 32768 pairs
    int o = idx >> 9, pair = idx & 511;
    int kc0 = pair * 2;
    int c = kc0 & 63, k = kc0 >> 6;
    float x0 = Wc[o * 1024 + c * 16 + k];
    float x1 = Wc[o * 1024 + (c + 1) * 16 + k];
    float r0, r1;
    uint32_t hw = pack_hi(x0, x1, r0, r1);
    uint32_t lw = pack_bf2(r0, r1);
    uint32_t* row = (uint32_t*)(g_WcPb + (size_t)o * 2048);
    row[pair] = hw;
    row[512 + pair] = lw;
}

// ---------------- bin: counting sort into 10^3 cells ----------------
__global__ __launch_bounds__(1024) void bin_kernel(const float* __restrict__ xyz) {
    __shared__ int cnt[NCELL];
    __shared__ int off[NCELL];
    __shared__ int wsum[32];
    int b = blockIdx.x, tid = threadIdx.x, lane = tid & 31, wid = tid >> 5;
    for (int i = tid; i < NCELL; i += 1024) cnt[i] = 0;
    __syncthreads();

    float xs[4], ys[4], zs[4];
    int cell[4];
    const float* xb = xyz + (size_t)b * NN * 3;
#pragma unroll
    for (int t = 0; t < 4; t++) {
        int n = tid * 4 + t;
        xs[t] = xb[n * 3 + 0];
        ys[t] = xb[n * 3 + 1];
        zs[t] = xb[n * 3 + 2];
        int ci = min((int)(xs[t] * 10.f), 9);
        int cj = min((int)(ys[t] * 10.f), 9);
        int ck = min((int)(zs[t] * 10.f), 9);
        cell[t] = (ck * 10 + cj) * 10 + ci;
        atomicAdd(&cnt[cell[t]], 1);
    }
    __syncthreads();

    int v = (tid < NCELL) ? cnt[tid] : 0;
    int orig = v;
#pragma unroll
    for (int d = 1; d < 32; d <<= 1) {
        int t2 = __shfl_up_sync(0xffffffffu, v, d);
        if (lane >= d) v += t2;
    }
    if (lane == 31) wsum[wid] = v;
    __syncthreads();
    if (wid == 0) {
        int s = wsum[lane];
#pragma unroll
        for (int d = 1; d < 32; d <<= 1) {
            int t2 = __shfl_up_sync(0xffffffffu, s, d);
            if (lane >= d) s += t2;
        }
        wsum[lane] = s;
    }
    __syncthreads();
    int excl = v + (wid > 0 ? wsum[wid - 1] : 0) - orig;
    if (tid < NCELL) {
        off[tid] = excl;
        g_cellStart[(size_t)b * (NCELL + 1) + tid] = excl;
    }
    if (tid == 0) g_cellStart[(size_t)b * (NCELL + 1) + NCELL] = NN;
    __syncthreads();

#pragma unroll
    for (int t = 0; t < 4; t++) {
        int n = tid * 4 + t;
        int pos = atomicAdd(&off[cell[t]], 1);
        g_pts4[(size_t)b * NN + pos] = make_float4(xs[t], ys[t], zs[t], __int_as_float(n));
    }
}

// ---------------- KNN: sorted-center shared scan + tight-filtered rank selection ----------------
// Centers taken in cell-sorted order: a warp's 4 centers share one union window.
#define KNN_SMEM (size_t)(8 * 4 * CAPK * 8 + (NCELL + 8) * 4 + 32 * 4)

#define RANK_LOOP(cd, Mlen, kk, rr)                                         \
    do {                                                                    \
        if ((Mlen) <= 64) {                                                 \
            for (int q = 0; q < (Mlen); q++) {                              \
                unsigned long long kq = (cd)[q];                            \
                rr[0] += (kq < kk[0]); rr[1] += (kq < kk[1]);               \
            }                                                               \
        } else if ((Mlen) <= 128) {                                         \
            for (int q = 0; q < (Mlen); q++) {                              \
                unsigned long long kq = (cd)[q];                            \
                rr[0] += (kq < kk[0]); rr[1] += (kq < kk[1]);               \
                rr[2] += (kq < kk[2]); rr[3] += (kq < kk[3]);               \
            }                                                               \
        } else {                                                            \
            for (int q = 0; q < (Mlen); q++) {                              \
                unsigned long long kq = (cd)[q];                            \
                rr[0] += (kq < kk[0]); rr[1] += (kq < kk[1]);               \
                rr[2] += (kq < kk[2]); rr[3] += (kq < kk[3]);               \
                rr[4] += (kq < kk[4]); rr[5] += (kq < kk[5]);               \
                rr[6] += (kq < kk[6]);                                      \
            }                                                               \
        }                                                                   \
    } while (0)

__global__ __launch_bounds__(256, 3) void knn_kernel() {
    extern __shared__ char smem_raw[];
    unsigned long long* candAll = (unsigned long long*)smem_raw;
    int* scell = (int*)(candAll + 8 * 4 * CAPK);
    int* scnt = scell + (NCELL + 8);

    int b = blockIdx.y, tid = threadIdx.x, w = tid >> 5, lane = tid & 31;
    const int* cs = g_cellStart + (size_t)b * (NCELL + 1);
    for (int i = tid; i < NCELL + 1; i += 256) scell[i] = cs[i];
    if (tid < 32) scnt[tid] = 0;
    __syncthreads();

    int nbase = blockIdx.x * 32 + w * 4;       // SORTED position base
    unsigned long long* cand0 = candAll + (size_t)w * 4 * CAPK;
    int* mycnt = scnt + w * 4;
    const float4* pts = g_pts4 + (size_t)b * NN;

    float cx[4], cy[4], cz[4];
    int oidx[4];
#pragma unroll
    for (int i = 0; i < 4; i++) {
        float4 c = pts[nbase + i];
        cx[i] = c.x; cy[i] = c.y; cz[i] = c.z;
        oidx[i] = __float_as_int(c.w);
    }

    // union window over the 4 (co-located) centers
    int xlo = 9, xhi = 0, ylo = 9, yhi = 0, zlo = 9, zhi = 0;
#pragma unroll
    for (int i = 0; i < 4; i++) {
        int cxi = min((int)(cx[i] * 10.f), 9);
        int cyi = min((int)(cy[i] * 10.f), 9);
        int czi = min((int)(cz[i] * 10.f), 9);
        xlo = min(xlo, max(cxi - 2, 0)); xhi = max(xhi, min(cxi + 2, 9));
        ylo = min(ylo, max(cyi - 2, 0)); yhi = max(yhi, min(cyi + 2, 9));
        zlo = min(zlo, max(czi - 2, 0)); zhi = max(zhi, min(czi + 2, 9));
    }

    // single shared scan: each loaded point feeds all 4 centers
    for (int zz = zlo; zz <= zhi; zz++) {
        for (int yy = ylo; yy <= yhi; yy++) {
            int rb = (zz * 10 + yy) * 10;
            int s = scell[rb + xlo], e = scell[rb + xhi + 1];
            for (int p = s + lane; p < e; p += 32) {
                float4 pt = pts[p];
                unsigned lowbase = ((unsigned)__float_as_int(pt.w) << 12) | (unsigned)p;
#pragma unroll
                for (int i = 0; i < 4; i++) {
                    float dx = pt.x - cx[i], dy = pt.y - cy[i], dz = pt.z - cz[i];
                    float d2 = fmaf(dx, dx, fmaf(dy, dy, dz * dz));
                    if (d2 <= R2C) {
                        int pos = atomicAdd(&mycnt[i], 1);
                        if (pos < CAPK)
                            cand0[i * CAPK + pos] =
                                ((unsigned long long)__float_as_uint(d2) << 32) | lowbase;
                    }
                }
            }
        }
    }
    __syncwarp();

#pragma unroll
    for (int i = 0; i < 4; i++) {
        size_t cg = (size_t)b * NN + oidx[i];
        int M = min(mycnt[i], CAPK);
        unsigned long long* cd = cand0 + i * CAPK;
        unsigned lmask = (1u << lane) - 1u;

        // slots >= M get self (gxyz = 0); only when M < 32
        if (lane >= M) {
            g_idx[cg * NS + lane] = oidx[i];
            g_gx[cg * NS + lane] = 0.0f;
            g_gy[cg * NS + lane] = 0.0f;
            g_gz[cg * NS + lane] = 0.0f;
        }

        unsigned long long k[7];
#pragma unroll
        for (int t = 0; t < 7; t++) {
            int p = lane + 32 * t;
            k[t] = (p < M) ? cd[p] : ~0ull;
        }
        unsigned bms[7];
        int Mt = 0;
#pragma unroll
        for (int t = 0; t < 7; t++) {
            bms[t] = __ballot_sync(0xffffffffu, k[t] < TIGHTKEY64);
            Mt += __popc(bms[t]);
        }

        if (Mt >= NS) {
            int base = 0;
#pragma unroll
            for (int t = 0; t < 7; t++) {
                if (k[t] < TIGHTKEY64)
                    cd[base + __popc(bms[t] & lmask)] = k[t];
                base += __popc(bms[t]);
            }
            __syncwarp();
            unsigned long long k2[7];
            int rr[7];
#pragma unroll
            for (int t = 0; t < 7; t++) {
                int p = lane + 32 * t;
                k2[t] = (p < Mt) ? cd[p] : ~0ull;
                rr[t] = 0;
            }
            RANK_LOOP(cd, Mt, k2, rr);
#pragma unroll
            for (int t = 0; t < 7; t++) {
                int p = lane + 32 * t;
                if (p < Mt && rr[t] < NS) {
                    int low = (int)(k2[t] & 0xffffffffull);
                    int jj = (low >> 12) & 0xFFF;
                    float4 p4 = pts[low & 0xFFF];
                    g_idx[cg * NS + rr[t]] = jj;
                    g_gx[cg * NS + rr[t]] = p4.x - cx[i];
                    g_gy[cg * NS + rr[t]] = p4.y - cy[i];
                    g_gz[cg * NS + rr[t]] = p4.z - cz[i];
                }
            }
        } else {
            int rr[7];
#pragma unroll
            for (int t = 0; t < 7; t++) rr[t] = 0;
            RANK_LOOP(cd, M, k, rr);
#pragma unroll
            for (int t = 0; t < 7; t++) {
                int p = lane + 32 * t;
                if (p < M && rr[t] < NS) {
                    int low = (int)(k[t] & 0xffffffffull);
                    int jj = (low >> 12) & 0xFFF;
                    float4 p4 = pts[low & 0xFFF];
                    g_idx[cg * NS + rr[t]] = jj;
                    g_gx[cg * NS + rr[t]] = p4.x - cx[i];
                    g_gy[cg * NS + rr[t]] = p4.y - cy[i];
                    g_gz[cg * NS + rr[t]] = p4.z - cz[i];
                }
            }
        }
        __syncwarp();
    }
}

// ---------------- projgen: MLP + normalize + rank-32 proj, bf16-split output ----------------
#define CW 2
__global__ __launch_bounds__(256) void projgen_kernel(
    const float* __restrict__ W1, const float* __restrict__ b1,
    const float* __restrict__ W2, const float* __restrict__ b2,
    const float* __restrict__ W3, const float* __restrict__ b3)
{
    __shared__ float swfAll[8][512];
    __shared__ int   snjAll[8][32];
    __shared__ float sW[448];

    int tid = threadIdx.x, w = tid >> 5, lane = tid & 31;
    if (tid < 24)  sW[tid] = W1[tid];
    if (tid < 8)   sW[24 + tid] = b1[tid];
    if (tid < 128) sW[32 + tid] = W2[tid];
    if (tid < 16)  sW[160 + tid] = b2[tid];
    sW[176 + tid] = W3[tid];
    if (tid < 16)  sW[432 + tid] = b3[tid];
    __syncthreads();

    float* swf = swfAll[w];
    int* snj = snjAll[w];

    for (int it = 0; it < CW; it++) {
        size_t cg = (size_t)blockIdx.x * (8 * CW) + w * CW + it;
        int bb = (int)(cg >> 12);

        int   nj = g_idx[cg * NS + lane];
        float gx = g_gx[cg * NS + lane];
        float gy = g_gy[cg * NS + lane];
        float gz = g_gz[cg * NS + lane];

        float h1[8];
#pragma unroll
        for (int o = 0; o < 8; o++)
            h1[o] = leaky(fmaf(sW[o*3+0], gx, fmaf(sW[o*3+1], gy, fmaf(sW[o*3+2], gz, sW[24+o]))));
        float h2[16];
#pragma unroll
        for (int o = 0; o < 16; o++) {
            float a = sW[160 + o];
#pragma unroll
            for (int i = 0; i < 8; i++) a = fmaf(sW[32 + o*8 + i], h1[i], a);
            h2[o] = leaky(a);
        }
        float wv[16], w2sum = 0.0f;
#pragma unroll
        for (int o = 0; o < 16; o++) {
            float a = sW[432 + o];
#pragma unroll
            for (int i = 0; i < 16; i++) a = fmaf(sW[176 + o*16 + i], h2[i], a);
            wv[o] = a; w2sum = fmaf(a, a, w2sum);
        }
        float inv1 = rsqrtf(fmaxf(w2sum, 1e-8f));

        float wn[16];
#pragma unroll
        for (int kk = 0; kk < 16; kk++) {
            float t = wv[kk] * wv[kk];
#pragma unroll
            for (int off = 16; off; off >>= 1) t += __shfl_xor_sync(0xffffffffu, t, off);
            float s2 = fmaxf(sqrtf(fmaxf(t, 1e-8f)), 1.0f);
            wn[kk] = wv[kk] * inv1 * (1.0f / s2);
        }

        float4* swf4 = (float4*)swf;
#pragma unroll
        for (int q = 0; q < 4; q++)
            swf4[q * 32 + lane] = make_float4(wn[4*q], wn[4*q+1], wn[4*q+2], wn[4*q+3]);
        snj[lane] = nj;
        __syncwarp();

        const float* fT = g_featT + (size_t)bb * NN * CC;
        float2 buf[8];
#pragma unroll
        for (int p = 0; p < 8; p++)
            buf[p] = *(const float2*)(fT + (size_t)snj[p] * CC + 2 * lane);

        float acc0[16], acc1[16];
#pragma unroll
        for (int kk = 0; kk < 16; kk++) { acc0[kk] = 0.0f; acc1[kk] = 0.0f; }

#pragma unroll
        for (int s = 0; s < 32; s++) {
            float2 f = buf[s & 7];
            if (s < 24)
                buf[s & 7] = *(const float2*)(fT + (size_t)snj[s + 8] * CC + 2 * lane);
            float4 q0 = swf4[s], q1 = swf4[32 + s], q2 = swf4[64 + s], q3 = swf4[96 + s];
            acc0[0]  = fmaf(q0.x, f.x, acc0[0]);  acc1[0]  = fmaf(q0.x, f.y, acc1[0]);
            acc0[1]  = fmaf(q0.y, f.x, acc0[1]);  acc1[1]  = fmaf(q0.y, f.y, acc1[1]);
            acc0[2]  = fmaf(q0.z, f.x, acc0[2]);  acc1[2]  = fmaf(q0.z, f.y, acc1[2]);
            acc0[3]  = fmaf(q0.w, f.x, acc0[3]);  acc1[3]  = fmaf(q0.w, f.y, acc1[3]);
            acc0[4]  = fmaf(q1.x, f.x, acc0[4]);  acc1[4]  = fmaf(q1.x, f.y, acc1[4]);
            acc0[5]  = fmaf(q1.y, f.x, acc0[5]);  acc1[5]  = fmaf(q1.y, f.y, acc1[5]);
            acc0[6]  = fmaf(q1.z, f.x, acc0[6]);  acc1[6]  = fmaf(q1.z, f.y, acc1[6]);
            acc0[7]  = fmaf(q1.w, f.x, acc0[7]);  acc1[7]  = fmaf(q1.w, f.y, acc1[7]);
            acc0[8]  = fmaf(q2.x, f.x, acc0[8]);  acc1[8]  = fmaf(q2.x, f.y, acc1[8]);
            acc0[9]  = fmaf(q2.y, f.x, acc0[9]);  acc1[9]  = fmaf(q2.y, f.y, acc1[9]);
            acc0[10] = fmaf(q2.z, f.x, acc0[10]); acc1[10] = fmaf(q2.z, f.y, acc1[10]);
            acc0[11] = fmaf(q2.w, f.x, acc0[11]); acc1[11] = fmaf(q2.w, f.y, acc1[11]);
            acc0[12] = fmaf(q3.x, f.x, acc0[12]); acc1[12] = fmaf(q3.x, f.y, acc1[12]);
            acc0[13] = fmaf(q3.y, f.x, acc0[13]); acc1[13] = fmaf(q3.y, f.y, acc1[13]);
            acc0[14] = fmaf(q3.z, f.x, acc0[14]); acc1[14] = fmaf(q3.z, f.y, acc1[14]);
            acc0[15] = fmaf(q3.w, f.x, acc0[15]); acc1[15] = fmaf(q3.w, f.y, acc1[15]);
        }

        uint32_t* row = (uint32_t*)(g_projLb + cg * 2048);
#pragma unroll
        for (int kk = 0; kk < 16; kk++) {
            float v0 = leaky(acc0[kk]), v1 = leaky(acc1[kk]);
            float r0, r1;
            uint32_t hw = pack_hi(v0, v1, r0, r1);
            uint32_t lw = pack_bf2(r0, r1);
            row[kk * 32 + lane] = hw;
            row[512 + kk * 32 + lane] = lw;
        }
        __syncwarp();
    }
}

// ---------------- GEMM (bf16 hi/lo split, m16n8k16) ----------------
#define AW (128 * 20)
#define BW (64 * 20)
#define STGW (2 * AW + 2 * BW)
#define GEMM_SMEM_BYTES (2 * STGW * 4)

__global__ __launch_bounds__(256) void gemm_bf16_kernel(
    const float* __restrict__ bc, float* __restrict__ out)
{
    extern __shared__ uint32_t smw[];
    int tid = threadIdx.x, lane = tid & 31, w = tid >> 5;
    size_t row0 = (size_t)blockIdx.x * 128;
    int b = (int)(row0 >> 12), n0 = (int)(row0 & 4095);

    int ar = tid >> 1, ahalf = tid & 1;
    int br = tid >> 2, bq = tid & 3;

    const uint32_t* rowA = (const uint32_t*)(g_projLb + (row0 + ar) * 2048);
    const uint32_t* rowB = (const uint32_t*)(g_WcPb + (size_t)br * 2048);

    int wi = (w & 3) * 32;
    int wj = (w >> 2) * 32;

    float acc[2][4][4];
#pragma unroll
    for (int i = 0; i < 2; i++)
#pragma unroll
        for (int j = 0; j < 4; j++)
#pragma unroll
            for (int q = 0; q < 4; q++) acc[i][j][q] = 0.0f;

    uint4 aH0, aH1, aL0, aL1, bH, bL;
    {
        const uint4* pAh = (const uint4*)(rowA + ahalf * 8);
        const uint4* pAl = (const uint4*)(rowA + 512 + ahalf * 8);
        aH0 = pAh[0]; aH1 = pAh[1]; aL0 = pAl[0]; aL1 = pAl[1];
        bH = *(const uint4*)(rowB + bq * 4);
        bL = *(const uint4*)(rowB + 512 + bq * 4);
    }
    {
        uint32_t* buf = smw;
        *(uint4*)(buf + ar * 20 + ahalf * 8)          = aH0;
        *(uint4*)(buf + ar * 20 + ahalf * 8 + 4)      = aH1;
        *(uint4*)(buf + AW + ar * 20 + ahalf * 8)     = aL0;
        *(uint4*)(buf + AW + ar * 20 + ahalf * 8 + 4) = aL1;
        *(uint4*)(buf + 2 * AW + br * 20 + bq * 4)          = bH;
        *(uint4*)(buf + 2 * AW + BW + br * 20 + bq * 4)     = bL;
    }
    __syncthreads();

    for (int s = 0; s < 32; s++) {
        if (s + 1 < 32) {
            int wb = (s + 1) * 16;
            const uint4* pAh = (const uint4*)(rowA + wb + ahalf * 8);
            const uint4* pAl = (const uint4*)(rowA + 512 + wb + ahalf * 8);
            aH0 = pAh[0]; aH1 = pAh[1]; aL0 = pAl[0]; aL1 = pAl[1];
            bH = *(const uint4*)(rowB + wb + bq * 4);
            bL = *(const uint4*)(rowB + 512 + wb + bq * 4);
        }
        const uint32_t* buf = smw + (s & 1) * STGW;
        const uint32_t* Ah = buf;
        const uint32_t* Al = buf + AW;
        const uint32_t* Bh = buf + 2 * AW;
        const uint32_t* Bl = buf + 2 * AW + BW;

#pragma unroll
        for (int t = 0; t < 2; t++) {
            int wb = t * 8;
            uint32_t ah[2][4], al[2][4];
#pragma unroll
            for (int ii = 0; ii < 2; ii++) {
                int r = wi + ii * 16 + (lane >> 2);
                int c0 = wb + (lane & 3);
                ah[ii][0] = Ah[r * 20 + c0];
                ah[ii][1] = Ah[(r + 8) * 20 + c0];
                ah[ii][2] = Ah[r * 20 + c0 + 4];
                ah[ii][3] = Ah[(r + 8) * 20 + c0 + 4];
                al[ii][0] = Al[r * 20 + c0];
                al[ii][1] = Al[(r + 8) * 20 + c0];
                al[ii][2] = Al[r * 20 + c0 + 4];
                al[ii][3] = Al[(r + 8) * 20 + c0 + 4];
            }
            uint32_t bh[4][2], bl[4][2];
#pragma unroll
            for (int jj = 0; jj < 4; jj++) {
                int n = wj + jj * 8 + (lane >> 2);
                int c0 = wb + (lane & 3);
                bh[jj][0] = Bh[n * 20 + c0];
                bh[jj][1] = Bh[n * 20 + c0 + 4];
                bl[jj][0] = Bl[n * 20 + c0];
                bl[jj][1] = Bl[n * 20 + c0 + 4];
            }
#pragma unroll
            for (int ii = 0; ii < 2; ii++)
#pragma unroll
                for (int jj = 0; jj < 4; jj++) {
                    mma_bf16(acc[ii][jj], ah[ii], bh[jj]);
                    mma_bf16(acc[ii][jj], ah[ii], bl[jj]);
                    mma_bf16(acc[ii][jj], al[ii], bh[jj]);
                }
        }

        if (s + 1 < 32) {
            uint32_t* nb = smw + ((s + 1) & 1) * STGW;
            *(uint4*)(nb + ar * 20 + ahalf * 8)          = aH0;
            *(uint4*)(nb + ar * 20 + ahalf * 8 + 4)      = aH1;
            *(uint4*)(nb + AW + ar * 20 + ahalf * 8)     = aL0;
            *(uint4*)(nb + AW + ar * 20 + ahalf * 8 + 4) = aL1;
            *(uint4*)(nb + 2 * AW + br * 20 + bq * 4)      = bH;
            *(uint4*)(nb + 2 * AW + BW + br * 20 + bq * 4) = bL;
        }
        __syncthreads();
    }

    float* sO = (float*)smw;
#pragma unroll
    for (int ii = 0; ii < 2; ii++)
#pragma unroll
        for (int jj = 0; jj < 4; jj++) {
            int r = wi + ii * 16 + (lane >> 2);
            int o = wj + jj * 8 + (lane & 3) * 2;
            float b0v = __ldg(&bc[o]), b1v = __ldg(&bc[o + 1]);
            sO[o * 140 + r]           = leaky(acc[ii][jj][0] + b0v);
            sO[(o + 1) * 140 + r]     = leaky(acc[ii][jj][1] + b1v);
            sO[o * 140 + r + 8]       = leaky(acc[ii][jj][2] + b0v);
            sO[(o + 1) * 140 + r + 8] = leaky(acc[ii][jj][3] + b1v);
        }
    __syncthreads();

    int oo = tid >> 2, c4 = (tid & 3) * 4;
    float* orow = out + (size_t)b * (OUTC * NN) + (size_t)oo * NN + n0;
#pragma unroll
    for (int q = 0; q < 8; q++) {
        float4 v = *(float4*)&sO[oo * 140 + c4 + q * 16];
        *(float4*)&orow[c4 + q * 16] = v;
    }
}

extern "C" void kernel_launch(void* const* d_in, const int* in_sizes, int n_in,
                              void* d_out, int out_size) {
    const float* xyz  = (const float*)d_in[0];
    const float* feat = (const float*)d_in[1];
    const float* W1 = (const float*)d_in[2];
    const float* b1 = (const float*)d_in[3];
    const float* W2 = (const float*)d_in[4];
    const float* b2 = (const float*)d_in[5];
    const float* W3 = (const float*)d_in[6];
    const float* b3 = (const float*)d_in[7];
    const float* Wc = (const float*)d_in[8];
    const float* bc = (const float*)d_in[9];

    float* out = (float*)d_out;
    float* out_main = out;
    const int xyz_elems = BB * NN * 3;
    const int out_elems = BB * OUTC * NN;
    if (out_size == xyz_elems + out_elems) {
        cudaMemcpyAsync(out, xyz, (size_t)xyz_elems * sizeof(float), cudaMemcpyDeviceToDevice);
        out_main = out + xyz_elems;
    }

    // ncu captures global launch index 3 -> knn_kernel
    transpose_kernel<<<dim3(NN / 32, CC / 32, BB), dim3(32, 8)>>>(feat);      // 0
    wcperm_kernel<<<(OUTC * 512) / 256, 256>>>(Wc);                            // 1
    bin_kernel<<<BB, 1024>>>(xyz);                                             // 2

    cudaFuncSetAttribute(knn_kernel, cudaFuncAttributeMaxDynamicSharedMemorySize, (int)KNN_SMEM);
    knn_kernel<<<dim3(NN / 32, BB), 256, KNN_SMEM>>>();                        // 3

    projgen_kernel<<<(BB * NN) / (8 * CW), 256>>>(W1, b1, W2, b2, W3, b3);     // 4

    cudaFuncSetAttribute(gemm_bf16_kernel, cudaFuncAttributeMaxDynamicSharedMemorySize, GEMM_SMEM_BYTES);
    gemm_bf16_kernel<<<(BB * NN) / 128, 256, GEMM_SMEM_BYTES>>>(bc, out_main); // 5
}